// round 10
// baseline (speedup 1.0000x reference)
#include <cuda_runtime.h>
#include <cuda_bf16.h>
#include <cuda_fp16.h>
#include <math.h>

typedef unsigned u32;

#define B_  32
#define TQ_ 1024
#define TK_ 1024
#define D_  64
#define STRD 72   // smem row stride in 2B elems (64 data + 8 pad): conflict-free frags
#define VSTR 68   // fp32 tile row stride (conflict-free for split reads)

// scratch: fp16 scores/probs, partial rowsums, precomputed operands
static __device__ __half g_S[(size_t)B_ * TQ_ * TK_];
static __device__ __half g_P[(size_t)B_ * TQ_ * TK_];
static __device__ float  g_psum[(size_t)B_ * TQ_ * 8];
static __device__ __nv_bfloat16 g_Qh[(size_t)B_ * TQ_ * D_];
static __device__ __nv_bfloat16 g_Ql[(size_t)B_ * TQ_ * D_];
static __device__ __nv_bfloat16 g_Kh[(size_t)B_ * TK_ * D_];
static __device__ __nv_bfloat16 g_Kl[(size_t)B_ * TK_ * D_];
static __device__ __half g_Vh[(size_t)B_ * D_ * TK_];   // V hi, [b][d][k]
static __device__ __half g_Vl[(size_t)B_ * D_ * TK_];   // V lo, [b][d][k]

// ---- mma helpers ----------------------------------------------------------
__device__ __forceinline__ void mma_bf16(float c[4], u32 a0, u32 a1, u32 a2, u32 a3,
                                         u32 b0, u32 b1)
{
    asm volatile(
        "mma.sync.aligned.m16n8k16.row.col.f32.bf16.bf16.f32 "
        "{%0,%1,%2,%3},{%4,%5,%6,%7},{%8,%9},{%0,%1,%2,%3};\n"
        : "+f"(c[0]), "+f"(c[1]), "+f"(c[2]), "+f"(c[3])
        : "r"(a0), "r"(a1), "r"(a2), "r"(a3), "r"(b0), "r"(b1));
}
__device__ __forceinline__ void mma_f16(float c[4], u32 a0, u32 a1, u32 a2, u32 a3,
                                        u32 b0, u32 b1)
{
    asm volatile(
        "mma.sync.aligned.m16n8k16.row.col.f32.f16.f16.f32 "
        "{%0,%1,%2,%3},{%4,%5,%6,%7},{%8,%9},{%0,%1,%2,%3};\n"
        : "+f"(c[0]), "+f"(c[1]), "+f"(c[2]), "+f"(c[3])
        : "r"(a0), "r"(a1), "r"(a2), "r"(a3), "r"(b0), "r"(b1));
}

__device__ __forceinline__ u32 cvt2bf(float hi, float lo) {
    u32 r;
    asm("cvt.rn.bf16x2.f32 %0,%1,%2;" : "=r"(r) : "f"(hi), "f"(lo));
    return r;
}
// bf16 hi/lo split (x0 -> low half, x1 -> high half)
__device__ __forceinline__ void split2(float x0, float x1, u32& h, u32& l) {
    h = cvt2bf(x1, x0);
    float h0 = __uint_as_float(h << 16);
    float h1 = __uint_as_float(h & 0xffff0000u);
    l = cvt2bf(x1 - h1, x0 - h0);
}
// fp16 hi/lo split
__device__ __forceinline__ void split2h(float x0, float x1, u32& h, u32& l) {
    __half2 hh = __floats2half2_rn(x0, x1);
    h = *(u32*)&hh;
    float2 hf = __half22float2(hh);
    __half2 ll = __floats2half2_rn(x0 - hf.x, x1 - hf.y);
    l = *(u32*)&ll;
}

// ---- cp.async helpers -----------------------------------------------------
__device__ __forceinline__ void cp16(void* dst_smem, const void* src) {
    u32 d = (u32)__cvta_generic_to_shared(dst_smem);
    asm volatile("cp.async.cg.shared.global [%0], [%1], 16;\n" :: "r"(d), "l"(src));
}
#define CP_COMMIT() asm volatile("cp.async.commit_group;\n" ::)
#define CP_WAIT1()  asm volatile("cp.async.wait_group 1;\n" ::)
#define CP_WAIT0()  asm volatile("cp.async.wait_group 0;\n" ::)

// ---------------------------------------------------------------------------
// Kernel P0: precompute bf16 hi/lo for Q and K (row-major, same layout)
// ---------------------------------------------------------------------------
extern "C" __global__ void __launch_bounds__(256)
prep_qk_kernel(const float* __restrict__ Q, const float* __restrict__ K)
{
    size_t idx = (size_t)blockIdx.x * 256 + threadIdx.x;
    float4 v = ((const float4*)Q)[idx];
    u32 h0, l0, h1, l1;
    split2(v.x, v.y, h0, l0); split2(v.z, v.w, h1, l1);
    ((uint2*)g_Qh)[idx] = make_uint2(h0, h1);
    ((uint2*)g_Ql)[idx] = make_uint2(l0, l1);
    float4 w = ((const float4*)K)[idx];
    split2(w.x, w.y, h0, l0); split2(w.z, w.w, h1, l1);
    ((uint2*)g_Kh)[idx] = make_uint2(h0, h1);
    ((uint2*)g_Kl)[idx] = make_uint2(l0, l1);
}

// ---------------------------------------------------------------------------
// Kernel P1: V -> fp16 hi/lo, transposed to [b][d][k]. grid (16, 32).
// ---------------------------------------------------------------------------
extern "C" __global__ void __launch_bounds__(256)
prep_v_kernel(const float* __restrict__ V)
{
    const int b  = blockIdx.y;
    const int kt = blockIdx.x * 64;
    __shared__ float Vt[64][VSTR];

    const int tid = threadIdx.x;
    const float* Vb = V + ((size_t)b * TK_ + kt) * D_;
#pragma unroll
    for (int i = 0; i < 4; i++) {
        int idx = tid + i * 256;
        int k  = idx >> 4;
        int dc = (idx & 15) * 4;
        *(float4*)&Vt[k][dc] = *(const float4*)(Vb + (size_t)k * D_ + dc);
    }
    __syncthreads();

    const int d  = tid >> 2;           // 0..63
    const int ks = (tid & 3) * 16;     // 16 k per thread
    u32 hh[8], ll[8];
#pragma unroll
    for (int j = 0; j < 8; j++)
        split2h(Vt[ks + 2 * j][d], Vt[ks + 2 * j + 1][d], hh[j], ll[j]);
    __half* dh = g_Vh + ((size_t)b * D_ + d) * TK_ + kt + ks;
    __half* dl = g_Vl + ((size_t)b * D_ + d) * TK_ + kt + ks;
    *(uint4*)(dh)     = make_uint4(hh[0], hh[1], hh[2], hh[3]);
    *(uint4*)(dh + 8) = make_uint4(hh[4], hh[5], hh[6], hh[7]);
    *(uint4*)(dl)     = make_uint4(ll[0], ll[1], ll[2], ll[3]);
    *(uint4*)(dl + 8) = make_uint4(ll[4], ll[5], ll[6], ll[7]);
}

// ---------------------------------------------------------------------------
// Kernel A: S[b,q,k] = Q[b,q,:]·K[b,k,:] (unscaled, fp16 out). bf16x3 MMA.
// ---------------------------------------------------------------------------
extern "C" __global__ void __launch_bounds__(256)
qk_kernel()
{
    const int bz = blockIdx.z;
    const int qt = blockIdx.y * 64;
    const int kt = blockIdx.x * 64;
    __half* Sb = g_S + (size_t)bz * TQ_ * TK_;

    __shared__ __nv_bfloat16 Ah[64][STRD], Al[64][STRD];
    __shared__ __nv_bfloat16 Bh[64][STRD], Bl[64][STRD];

    const int tid = threadIdx.x;
    {
        const __nv_bfloat16* qh = g_Qh + ((size_t)bz * TQ_ + qt) * D_;
        const __nv_bfloat16* ql = g_Ql + ((size_t)bz * TQ_ + qt) * D_;
        const __nv_bfloat16* kh = g_Kh + ((size_t)bz * TK_ + kt) * D_;
        const __nv_bfloat16* kl = g_Kl + ((size_t)bz * TK_ + kt) * D_;
#pragma unroll
        for (int i = 0; i < 2; i++) {
            int idx = tid + i * 256;
            int row = idx >> 3;
            int c8  = (idx & 7) * 8;
            cp16(&Ah[row][c8], qh + row * D_ + c8);
            cp16(&Al[row][c8], ql + row * D_ + c8);
            cp16(&Bh[row][c8], kh + row * D_ + c8);
            cp16(&Bl[row][c8], kl + row * D_ + c8);
        }
    }
    CP_COMMIT();
    CP_WAIT0();
    __syncthreads();

    const int wid = tid >> 5, lane = tid & 31;
    const int g = lane >> 2, tg = lane & 3;
    const int wm = (wid >> 2) * 32;
    const int wn = (wid & 3) * 16;

    float c[2][2][4] = {};

#pragma unroll
    for (int k0 = 0; k0 < 64; k0 += 16) {
        u32 ah[2][4], al[2][4], bh[2][2], bl[2][2];
#pragma unroll
        for (int mi = 0; mi < 2; mi++) {
            const __nv_bfloat16* ph = &Ah[wm + mi * 16 + g][k0 + 2 * tg];
            ah[mi][0] = *(const u32*)(ph);
            ah[mi][1] = *(const u32*)(ph + 8 * STRD);
            ah[mi][2] = *(const u32*)(ph + 8);
            ah[mi][3] = *(const u32*)(ph + 8 * STRD + 8);
            const __nv_bfloat16* pl = &Al[wm + mi * 16 + g][k0 + 2 * tg];
            al[mi][0] = *(const u32*)(pl);
            al[mi][1] = *(const u32*)(pl + 8 * STRD);
            al[mi][2] = *(const u32*)(pl + 8);
            al[mi][3] = *(const u32*)(pl + 8 * STRD + 8);
        }
#pragma unroll
        for (int ni = 0; ni < 2; ni++) {
            const __nv_bfloat16* ph = &Bh[wn + ni * 8 + g][k0 + 2 * tg];
            bh[ni][0] = *(const u32*)(ph);
            bh[ni][1] = *(const u32*)(ph + 8);
            const __nv_bfloat16* pl = &Bl[wn + ni * 8 + g][k0 + 2 * tg];
            bl[ni][0] = *(const u32*)(pl);
            bl[ni][1] = *(const u32*)(pl + 8);
        }
#pragma unroll
        for (int mi = 0; mi < 2; mi++)
#pragma unroll
            for (int ni = 0; ni < 2; ni++) {
                mma_bf16(c[mi][ni], ah[mi][0], ah[mi][1], ah[mi][2], ah[mi][3],
                         bh[ni][0], bh[ni][1]);
                mma_bf16(c[mi][ni], al[mi][0], al[mi][1], al[mi][2], al[mi][3],
                         bh[ni][0], bh[ni][1]);
                mma_bf16(c[mi][ni], ah[mi][0], ah[mi][1], ah[mi][2], ah[mi][3],
                         bl[ni][0], bl[ni][1]);
            }
    }

#pragma unroll
    for (int mi = 0; mi < 2; mi++)
#pragma unroll
        for (int ni = 0; ni < 2; ni++) {
            int m = qt + wm + mi * 16 + g;
            int n = kt + wn + ni * 8 + 2 * tg;
            *(__half2*)&Sb[(size_t)m * TK_ + n] =
                __floats2half2_rn(c[mi][ni][0], c[mi][ni][1]);
            *(__half2*)&Sb[(size_t)(m + 8) * TK_ + n] =
                __floats2half2_rn(c[mi][ni][2], c[mi][ni][3]);
        }
}

// ---------------------------------------------------------------------------
// Kernel B: P(fp16) = exp(mask((S + Q·pos_k)/8)); emits partial rowsums.
// ---------------------------------------------------------------------------
__device__ __forceinline__ int bswz(int n, int c) {
    return n * 64 + ((((c >> 2) ^ (n & 7)) << 2) | (c & 3));
}

extern "C" __global__ void __launch_bounds__(256)
posk_kernel(const float* __restrict__ PK, const int* __restrict__ VL)
{
    const int q  = blockIdx.y;
    const int kt = blockIdx.x * 128;

    __shared__ __nv_bfloat16 Ah[32][STRD], Al[32][STRD];
    __shared__ float Bs[128 * 64];
    __shared__ float rsum[32][8];
    __shared__ int vls[B_];

    const int tid = threadIdx.x;
    {
        int row = tid >> 3;
        int c8  = (tid & 7) * 8;
        cp16(&Ah[row][c8], g_Qh + ((size_t)row * TQ_ + q) * D_ + c8);
        cp16(&Al[row][c8], g_Ql + ((size_t)row * TQ_ + q) * D_ + c8);
    }
    {
        const float* PKq = PK + ((size_t)q * TK_ + kt) * D_;
#pragma unroll
        for (int i = 0; i < 8; i++) {
            int idx = tid + i * 256;
            int row = idx >> 4;
            int c4  = idx & 15;
            cp16(&Bs[row * 64 + ((c4 ^ (row & 7)) << 2)], PKq + row * 64 + c4 * 4);
        }
    }
    CP_COMMIT();
    if (tid < B_) vls[tid] = VL[tid];
    CP_WAIT0();
    __syncthreads();

    const int wid = tid >> 5, lane = tid & 31;
    const int g = lane >> 2, tg = lane & 3;
    const int wn = wid * 16;

    float c[2][2][4] = {};

#pragma unroll
    for (int k0 = 0; k0 < 64; k0 += 16) {
        u32 ah[2][4], al[2][4], bh[2][2], bl[2][2];
#pragma unroll
        for (int mi = 0; mi < 2; mi++) {
            const __nv_bfloat16* ph = &Ah[mi * 16 + g][k0 + 2 * tg];
            ah[mi][0] = *(const u32*)(ph);
            ah[mi][1] = *(const u32*)(ph + 8 * STRD);
            ah[mi][2] = *(const u32*)(ph + 8);
            ah[mi][3] = *(const u32*)(ph + 8 * STRD + 8);
            const __nv_bfloat16* pl = &Al[mi * 16 + g][k0 + 2 * tg];
            al[mi][0] = *(const u32*)(pl);
            al[mi][1] = *(const u32*)(pl + 8 * STRD);
            al[mi][2] = *(const u32*)(pl + 8);
            al[mi][3] = *(const u32*)(pl + 8 * STRD + 8);
        }
#pragma unroll
        for (int ni = 0; ni < 2; ni++) {
            const int n = wn + ni * 8 + g;
            float2 v0 = *(const float2*)&Bs[bswz(n, k0 + 2 * tg)];
            split2(v0.x, v0.y, bh[ni][0], bl[ni][0]);
            float2 v1 = *(const float2*)&Bs[bswz(n, k0 + 2 * tg + 8)];
            split2(v1.x, v1.y, bh[ni][1], bl[ni][1]);
        }
#pragma unroll
        for (int mi = 0; mi < 2; mi++)
#pragma unroll
            for (int ni = 0; ni < 2; ni++) {
                mma_bf16(c[mi][ni], ah[mi][0], ah[mi][1], ah[mi][2], ah[mi][3],
                         bh[ni][0], bh[ni][1]);
                mma_bf16(c[mi][ni], al[mi][0], al[mi][1], al[mi][2], al[mi][3],
                         bh[ni][0], bh[ni][1]);
                mma_bf16(c[mi][ni], ah[mi][0], ah[mi][1], ah[mi][2], ah[mi][3],
                         bl[ni][0], bl[ni][1]);
            }
    }

    float rs[2][2] = {};
#pragma unroll
    for (int mi = 0; mi < 2; mi++) {
        const int b0  = mi * 16 + g;
        const int b1  = b0 + 8;
        const int vl0 = vls[b0];
        const int vl1 = vls[b1];
#pragma unroll
        for (int ni = 0; ni < 2; ni++) {
            const int col = kt + wn + ni * 8 + 2 * tg;
            {
                float2 s0 = __half22float2(
                    *(const __half2*)&g_S[((size_t)b0 * TQ_ + q) * TK_ + col]);
                float e0 = (col     < vl0) ? __expf((s0.x + c[mi][ni][0]) * 0.125f) : 0.f;
                float e1 = (col + 1 < vl0) ? __expf((s0.y + c[mi][ni][1]) * 0.125f) : 0.f;
                __half2 hp = __floats2half2_rn(e0, e1);
                *(__half2*)&g_P[((size_t)b0 * TQ_ + q) * TK_ + col] = hp;
                float2 er = __half22float2(hp);
                rs[mi][0] += er.x + er.y;
            }
            {
                float2 s1 = __half22float2(
                    *(const __half2*)&g_S[((size_t)b1 * TQ_ + q) * TK_ + col]);
                float e0 = (col     < vl1) ? __expf((s1.x + c[mi][ni][2]) * 0.125f) : 0.f;
                float e1 = (col + 1 < vl1) ? __expf((s1.y + c[mi][ni][3]) * 0.125f) : 0.f;
                __half2 hp = __floats2half2_rn(e0, e1);
                *(__half2*)&g_P[((size_t)b1 * TQ_ + q) * TK_ + col] = hp;
                float2 er = __half22float2(hp);
                rs[mi][1] += er.x + er.y;
            }
        }
    }
#pragma unroll
    for (int mi = 0; mi < 2; mi++)
#pragma unroll
        for (int r = 0; r < 2; r++) {
            rs[mi][r] += __shfl_xor_sync(0xffffffffu, rs[mi][r], 1);
            rs[mi][r] += __shfl_xor_sync(0xffffffffu, rs[mi][r], 2);
        }
    if (tg == 0) {
#pragma unroll
        for (int mi = 0; mi < 2; mi++) {
            rsum[mi * 16 + g][wid]     = rs[mi][0];
            rsum[mi * 16 + g + 8][wid] = rs[mi][1];
        }
    }
    __syncthreads();
    if (tid < 32) {
        float4 a = *(float4*)&rsum[tid][0];
        float4 b = *(float4*)&rsum[tid][4];
        g_psum[((size_t)tid * TQ_ + q) * 8 + blockIdx.x] =
            ((a.x + a.y) + (a.z + a.w)) + ((b.x + b.y) + (b.z + b.w));
    }
}

// ---------------------------------------------------------------------------
// Kernel C: O = (1/sum) * P(fp16) · V. grid (16,32). f16 MMA.
// 2-stage cp.async pipeline; V pre-split fp16 [b][d][k] -> direct B-frag LDS.
// ---------------------------------------------------------------------------
#define PV_STAGE_H  (64 * STRD)                 // halves per (P|Vh|Vl) stage
#define PV_SMEM     (3 * 2 * PV_STAGE_H * 2 + 64 * 4)

extern "C" __global__ void __launch_bounds__(256)
pv_kernel(float* __restrict__ Out)
{
    extern __shared__ char dynbuf[];
    __half* PhB  = (__half*)dynbuf;                              // [2][64][STRD]
    __half* VhB  = PhB + 2 * PV_STAGE_H;                         // [2][64][STRD]
    __half* VlB  = VhB + 2 * PV_STAGE_H;                         // [2][64][STRD]
    float*  invs = (float*)(VlB + 2 * PV_STAGE_H);

    const int bz = blockIdx.y;
    const int qt = blockIdx.x * 64;
    const __half* Pb  = g_P  + (size_t)bz * TQ_ * TK_;
    const __half* Vhb = g_Vh + (size_t)bz * D_ * TK_;
    const __half* Vlb = g_Vl + (size_t)bz * D_ * TK_;

    const int tid = threadIdx.x;
    if (tid < 64) {
        const float* ps = &g_psum[((size_t)bz * TQ_ + qt + tid) * 8];
        float4 a = *(const float4*)ps;
        float4 b = *(const float4*)(ps + 4);
        invs[tid] = 1.0f / (((a.x + a.y) + (a.z + a.w)) + ((b.x + b.y) + (b.z + b.w)));
    }

    auto load_stage = [&](int s, int kt) {
        __half* Ph = PhB + s * PV_STAGE_H;
        __half* Vh = VhB + s * PV_STAGE_H;
        __half* Vl = VlB + s * PV_STAGE_H;
#pragma unroll
        for (int i = 0; i < 2; i++) {          // P: 512 x 16B (64 rows x 4)
            int idx = tid + i * 256;
            int r  = idx >> 3;
            int kc = (idx & 7) * 8;
            cp16(Ph + r * STRD + kc, Pb + (size_t)(qt + r) * TK_ + kt + kc);
        }
        {                                       // Vh: 256 x 16B (64 rows x 4)
            int d  = tid >> 2;
            int kc = (tid & 3) * 16;
            cp16(Vh + d * STRD + kc,     Vhb + (size_t)d * TK_ + kt + kc);
            cp16(Vh + d * STRD + kc + 8, Vhb + (size_t)d * TK_ + kt + kc + 8);
            cp16(Vl + d * STRD + kc,     Vlb + (size_t)d * TK_ + kt + kc);
            cp16(Vl + d * STRD + kc + 8, Vlb + (size_t)d * TK_ + kt + kc + 8);
        }
        CP_COMMIT();
    };

    const int wid = tid >> 5, lane = tid & 31;
    const int g = lane >> 2, tg = lane & 3;
    const int wm = (wid >> 2) * 32;
    const int wn = (wid & 3) * 16;

    float c[2][2][4] = {};

    load_stage(0, 0);
    for (int ci = 0; ci < 16; ci++) {
        const int s = ci & 1;
        if (ci < 15) { load_stage(s ^ 1, (ci + 1) * 64); CP_WAIT1(); }
        else         { CP_WAIT0(); }
        __syncthreads();

        const __half* Ph = PhB + s * PV_STAGE_H;
        const __half* Vh = VhB + s * PV_STAGE_H;
        const __half* Vl = VlB + s * PV_STAGE_H;
#pragma unroll
        for (int k0 = 0; k0 < 64; k0 += 16) {
            u32 a[2][4], bh[2][2], bl[2][2];
#pragma unroll
            for (int mi = 0; mi < 2; mi++) {
                const __half* ph = Ph + (wm + mi * 16 + g) * STRD + k0 + 2 * tg;
                a[mi][0] = *(const u32*)(ph);
                a[mi][1] = *(const u32*)(ph + 8 * STRD);
                a[mi][2] = *(const u32*)(ph + 8);
                a[mi][3] = *(const u32*)(ph + 8 * STRD + 8);
            }
#pragma unroll
            for (int ni = 0; ni < 2; ni++) {
                const __half* vh = Vh + (wn + ni * 8 + g) * STRD + k0 + 2 * tg;
                bh[ni][0] = *(const u32*)(vh);
                bh[ni][1] = *(const u32*)(vh + 8);
                const __half* vl = Vl + (wn + ni * 8 + g) * STRD + k0 + 2 * tg;
                bl[ni][0] = *(const u32*)(vl);
                bl[ni][1] = *(const u32*)(vl + 8);
            }
#pragma unroll
            for (int mi = 0; mi < 2; mi++)
#pragma unroll
                for (int ni = 0; ni < 2; ni++) {
                    mma_f16(c[mi][ni], a[mi][0], a[mi][1], a[mi][2], a[mi][3],
                            bh[ni][0], bh[ni][1]);
                    mma_f16(c[mi][ni], a[mi][0], a[mi][1], a[mi][2], a[mi][3],
                            bl[ni][0], bl[ni][1]);
                }
        }
        __syncthreads();
    }

#pragma unroll
    for (int mi = 0; mi < 2; mi++)
#pragma unroll
        for (int ni = 0; ni < 2; ni++) {
            int m = wm + mi * 16 + g;
            int n = wn + ni * 8 + 2 * tg;
            float inv0 = invs[m], inv1 = invs[m + 8];
            float* d0 = Out + ((size_t)bz * TQ_ + qt + m) * D_ + n;
            *(float2*)d0 = make_float2(c[mi][ni][0] * inv0, c[mi][ni][1] * inv0);
            float* d1 = Out + ((size_t)bz * TQ_ + qt + m + 8) * D_ + n;
            *(float2*)d1 = make_float2(c[mi][ni][2] * inv1, c[mi][ni][3] * inv1);
        }
}

// ---------------------------------------------------------------------------
// Kernel D: O += (1/sum) * P(fp16) · pos_v[q]. grid (1024). f16 MMA.
// 2-stage cp.async pipeline (measured best); static smem.
// ---------------------------------------------------------------------------
extern "C" __global__ void __launch_bounds__(256)
posv_kernel(const float* __restrict__ PV, float* __restrict__ Out)
{
    const int q = blockIdx.x;

    __shared__ __half Ahs[2][32][STRD];   // P chunks fp16
    __shared__ float  PVs[2][64][VSTR];   // pos_v chunks fp32 [k][d]
    __shared__ float  invs[B_];

    const int tid = threadIdx.x;
    if (tid < B_) {
        const float* ps = &g_psum[((size_t)tid * TQ_ + q) * 8];
        float4 a = *(const float4*)ps;
        float4 b = *(const float4*)(ps + 4);
        invs[tid] = 1.0f / (((a.x + a.y) + (a.z + a.w)) + ((b.x + b.y) + (b.z + b.w)));
    }

    auto load_stage = [&](int s, int kt) {
        {
            int bb = tid >> 3;
            int kc = (tid & 7) * 8;
            cp16(&Ahs[s][bb][kc], g_P + ((size_t)bb * TQ_ + q) * TK_ + kt + kc);
        }
        const float* PVq = PV + ((size_t)q * TK_ + kt) * D_;
#pragma unroll
        for (int i = 0; i < 4; i++) {
            int idx = tid + i * 256;
            int k  = idx >> 4;
            int dc = (idx & 15) * 4;
            cp16(&PVs[s][k][dc], PVq + (size_t)k * D_ + dc);
        }
        CP_COMMIT();
    };

    const int wid = tid >> 5, lane = tid & 31;
    const int g = lane >> 2, tg = lane & 3;
    const int wn = wid * 8;

    float c[2][4] = {};

    load_stage(0, 0);
    for (int ci = 0; ci < 16; ci++) {
        const int s = ci & 1;
        if (ci < 15) { load_stage(s ^ 1, (ci + 1) * 64); CP_WAIT1(); }
        else         { CP_WAIT0(); }
        __syncthreads();

#pragma unroll
        for (int k0 = 0; k0 < 64; k0 += 16) {
            u32 a[2][4], bh[2], bl[2];
#pragma unroll
            for (int mi = 0; mi < 2; mi++) {
                const __half* ph = &Ahs[s][mi * 16 + g][k0 + 2 * tg];
                a[mi][0] = *(const u32*)(ph);
                a[mi][1] = *(const u32*)(ph + 8 * STRD);
                a[mi][2] = *(const u32*)(ph + 8);
                a[mi][3] = *(const u32*)(ph + 8 * STRD + 8);
            }
            {
                const int n = wn + g;
                const int kb = k0 + 2 * tg;
                split2h(PVs[s][kb][n],     PVs[s][kb + 1][n], bh[0], bl[0]);
                split2h(PVs[s][kb + 8][n], PVs[s][kb + 9][n], bh[1], bl[1]);
            }
#pragma unroll
            for (int mi = 0; mi < 2; mi++) {
                mma_f16(c[mi], a[mi][0], a[mi][1], a[mi][2], a[mi][3], bh[0], bh[1]);
                mma_f16(c[mi], a[mi][0], a[mi][1], a[mi][2], a[mi][3], bl[0], bl[1]);
            }
        }
        __syncthreads();
    }

#pragma unroll
    for (int mi = 0; mi < 2; mi++) {
        const int b0 = mi * 16 + g;
        const int b1 = b0 + 8;
        const int n  = wn + 2 * tg;
        float* d0 = Out + ((size_t)b0 * TQ_ + q) * D_ + n;
        float2 o0 = *(float2*)d0;
        o0.x += c[mi][0] * invs[b0];
        o0.y += c[mi][1] * invs[b0];
        *(float2*)d0 = o0;
        float* d1 = Out + ((size_t)b1 * TQ_ + q) * D_ + n;
        float2 o1 = *(float2*)d1;
        o1.x += c[mi][2] * invs[b1];
        o1.y += c[mi][3] * invs[b1];
        *(float2*)d1 = o1;
    }
}

// ---------------------------------------------------------------------------
extern "C" void kernel_launch(void* const* d_in, const int* in_sizes, int n_in,
                              void* d_out, int out_size)
{
    const float* Q  = (const float*)d_in[0];
    const float* K  = (const float*)d_in[1];
    const float* V  = (const float*)d_in[2];
    const float* PK = (const float*)d_in[3];
    const float* PV = (const float*)d_in[4];
    const int*   VL = (const int*)d_in[5];
    float* Out = (float*)d_out;

    cudaFuncSetAttribute(pv_kernel, cudaFuncAttributeMaxDynamicSharedMemorySize,
                         PV_SMEM);

    prep_qk_kernel<<<2048, 256>>>(Q, K);
    prep_v_kernel<<<dim3(16, 32), 256>>>(V);
    qk_kernel<<<dim3(TK_ / 64, TQ_ / 64, B_), 256>>>();
    posk_kernel<<<dim3(TK_ / 128, TQ_), 256>>>(PK, VL);
    pv_kernel<<<dim3(TQ_ / 64, B_), 256, PV_SMEM>>>(Out);
    posv_kernel<<<TQ_, 256>>>(PV, Out);
}

// round 11
// speedup vs baseline: 1.1129x; 1.1129x over previous
#include <cuda_runtime.h>
#include <cuda_bf16.h>
#include <cuda_fp16.h>
#include <math.h>

typedef unsigned u32;

#define B_  32
#define TQ_ 1024
#define TK_ 1024
#define D_  64
#define STRD 72   // smem row stride in 2B elems (64 data + 8 pad): conflict-free frags
#define VSTR 68   // fp32 tile row stride (conflict-free for split reads)

// scratch: fp16 scores/probs, partial rowsums, precomputed bf16 hi/lo Q,K
static __device__ __half g_S[(size_t)B_ * TQ_ * TK_];
static __device__ __half g_P[(size_t)B_ * TQ_ * TK_];
static __device__ float  g_psum[(size_t)B_ * TQ_ * 8];
static __device__ __nv_bfloat16 g_Qh[(size_t)B_ * TQ_ * D_];
static __device__ __nv_bfloat16 g_Ql[(size_t)B_ * TQ_ * D_];
static __device__ __nv_bfloat16 g_Kh[(size_t)B_ * TK_ * D_];
static __device__ __nv_bfloat16 g_Kl[(size_t)B_ * TK_ * D_];

// ---- mma helpers ----------------------------------------------------------
__device__ __forceinline__ void mma_bf16(float c[4], u32 a0, u32 a1, u32 a2, u32 a3,
                                         u32 b0, u32 b1)
{
    asm volatile(
        "mma.sync.aligned.m16n8k16.row.col.f32.bf16.bf16.f32 "
        "{%0,%1,%2,%3},{%4,%5,%6,%7},{%8,%9},{%0,%1,%2,%3};\n"
        : "+f"(c[0]), "+f"(c[1]), "+f"(c[2]), "+f"(c[3])
        : "r"(a0), "r"(a1), "r"(a2), "r"(a3), "r"(b0), "r"(b1));
}
__device__ __forceinline__ void mma_f16(float c[4], u32 a0, u32 a1, u32 a2, u32 a3,
                                        u32 b0, u32 b1)
{
    asm volatile(
        "mma.sync.aligned.m16n8k16.row.col.f32.f16.f16.f32 "
        "{%0,%1,%2,%3},{%4,%5,%6,%7},{%8,%9},{%0,%1,%2,%3};\n"
        : "+f"(c[0]), "+f"(c[1]), "+f"(c[2]), "+f"(c[3])
        : "r"(a0), "r"(a1), "r"(a2), "r"(a3), "r"(b0), "r"(b1));
}

__device__ __forceinline__ u32 cvt2bf(float hi, float lo) {
    u32 r;
    asm("cvt.rn.bf16x2.f32 %0,%1,%2;" : "=r"(r) : "f"(hi), "f"(lo));
    return r;
}
// bf16 hi/lo split (x0 -> low half, x1 -> high half)
__device__ __forceinline__ void split2(float x0, float x1, u32& h, u32& l) {
    h = cvt2bf(x1, x0);
    float h0 = __uint_as_float(h << 16);
    float h1 = __uint_as_float(h & 0xffff0000u);
    l = cvt2bf(x1 - h1, x0 - h0);
}
// fp16 hi/lo split
__device__ __forceinline__ void split2h(float x0, float x1, u32& h, u32& l) {
    __half2 hh = __floats2half2_rn(x0, x1);
    h = *(u32*)&hh;
    float2 hf = __half22float2(hh);
    __half2 ll = __floats2half2_rn(x0 - hf.x, x1 - hf.y);
    l = *(u32*)&ll;
}

// ---- cp.async helpers -----------------------------------------------------
__device__ __forceinline__ void cp16(void* dst_smem, const void* src) {
    u32 d = (u32)__cvta_generic_to_shared(dst_smem);
    asm volatile("cp.async.cg.shared.global [%0], [%1], 16;\n" :: "r"(d), "l"(src));
}
#define CP_COMMIT() asm volatile("cp.async.commit_group;\n" ::)
#define CP_WAIT1()  asm volatile("cp.async.wait_group 1;\n" ::)
#define CP_WAIT0()  asm volatile("cp.async.wait_group 0;\n" ::)

// ---------------------------------------------------------------------------
// Kernel P0: precompute bf16 hi/lo for Q and K (row-major, same layout)
// ---------------------------------------------------------------------------
extern "C" __global__ void __launch_bounds__(256)
prep_qk_kernel(const float* __restrict__ Q, const float* __restrict__ K)
{
    size_t idx = (size_t)blockIdx.x * 256 + threadIdx.x;
    float4 v = ((const float4*)Q)[idx];
    u32 h0, l0, h1, l1;
    split2(v.x, v.y, h0, l0); split2(v.z, v.w, h1, l1);
    ((uint2*)g_Qh)[idx] = make_uint2(h0, h1);
    ((uint2*)g_Ql)[idx] = make_uint2(l0, l1);
    float4 w = ((const float4*)K)[idx];
    split2(w.x, w.y, h0, l0); split2(w.z, w.w, h1, l1);
    ((uint2*)g_Kh)[idx] = make_uint2(h0, h1);
    ((uint2*)g_Kl)[idx] = make_uint2(l0, l1);
}

// ---------------------------------------------------------------------------
// Kernel A: S[b,q,k] = Q[b,q,:]·K[b,k,:] (unscaled, fp16 out). bf16x3 MMA.
// Epilogue stages result to smem, then writes S in coalesced 128B rows.
// ---------------------------------------------------------------------------
extern "C" __global__ void __launch_bounds__(256)
qk_kernel()
{
    const int bz = blockIdx.z;
    const int qt = blockIdx.y * 64;
    const int kt = blockIdx.x * 64;
    __half* Sb = g_S + (size_t)bz * TQ_ * TK_;

    __shared__ __nv_bfloat16 Ah[64][STRD], Al[64][STRD];
    __shared__ __nv_bfloat16 Bh[64][STRD], Bl[64][STRD];

    const int tid = threadIdx.x;
    {
        const __nv_bfloat16* qh = g_Qh + ((size_t)bz * TQ_ + qt) * D_;
        const __nv_bfloat16* ql = g_Ql + ((size_t)bz * TQ_ + qt) * D_;
        const __nv_bfloat16* kh = g_Kh + ((size_t)bz * TK_ + kt) * D_;
        const __nv_bfloat16* kl = g_Kl + ((size_t)bz * TK_ + kt) * D_;
#pragma unroll
        for (int i = 0; i < 2; i++) {
            int idx = tid + i * 256;
            int row = idx >> 3;
            int c8  = (idx & 7) * 8;
            cp16(&Ah[row][c8], qh + row * D_ + c8);
            cp16(&Al[row][c8], ql + row * D_ + c8);
            cp16(&Bh[row][c8], kh + row * D_ + c8);
            cp16(&Bl[row][c8], kl + row * D_ + c8);
        }
    }
    CP_COMMIT();
    CP_WAIT0();
    __syncthreads();

    const int wid = tid >> 5, lane = tid & 31;
    const int g = lane >> 2, tg = lane & 3;
    const int wm = (wid >> 2) * 32;
    const int wn = (wid & 3) * 16;

    float c[2][2][4] = {};

#pragma unroll
    for (int k0 = 0; k0 < 64; k0 += 16) {
        u32 ah[2][4], al[2][4], bh[2][2], bl[2][2];
#pragma unroll
        for (int mi = 0; mi < 2; mi++) {
            const __nv_bfloat16* ph = &Ah[wm + mi * 16 + g][k0 + 2 * tg];
            ah[mi][0] = *(const u32*)(ph);
            ah[mi][1] = *(const u32*)(ph + 8 * STRD);
            ah[mi][2] = *(const u32*)(ph + 8);
            ah[mi][3] = *(const u32*)(ph + 8 * STRD + 8);
            const __nv_bfloat16* pl = &Al[wm + mi * 16 + g][k0 + 2 * tg];
            al[mi][0] = *(const u32*)(pl);
            al[mi][1] = *(const u32*)(pl + 8 * STRD);
            al[mi][2] = *(const u32*)(pl + 8);
            al[mi][3] = *(const u32*)(pl + 8 * STRD + 8);
        }
#pragma unroll
        for (int ni = 0; ni < 2; ni++) {
            const __nv_bfloat16* ph = &Bh[wn + ni * 8 + g][k0 + 2 * tg];
            bh[ni][0] = *(const u32*)(ph);
            bh[ni][1] = *(const u32*)(ph + 8);
            const __nv_bfloat16* pl = &Bl[wn + ni * 8 + g][k0 + 2 * tg];
            bl[ni][0] = *(const u32*)(pl);
            bl[ni][1] = *(const u32*)(pl + 8);
        }
#pragma unroll
        for (int mi = 0; mi < 2; mi++)
#pragma unroll
            for (int ni = 0; ni < 2; ni++) {
                mma_bf16(c[mi][ni], ah[mi][0], ah[mi][1], ah[mi][2], ah[mi][3],
                         bh[ni][0], bh[ni][1]);
                mma_bf16(c[mi][ni], al[mi][0], al[mi][1], al[mi][2], al[mi][3],
                         bh[ni][0], bh[ni][1]);
                mma_bf16(c[mi][ni], ah[mi][0], ah[mi][1], ah[mi][2], ah[mi][3],
                         bl[ni][0], bl[ni][1]);
            }
    }

    // stage to smem (reuse Ah), then coalesced 128B-row stores to g_S
    __syncthreads();
    __half* Es = (__half*)Ah;   // viewed as [64][STRD]
#pragma unroll
    for (int mi = 0; mi < 2; mi++)
#pragma unroll
        for (int ni = 0; ni < 2; ni++) {
            int ml = wm + mi * 16 + g;
            int nl = wn + ni * 8 + 2 * tg;
            *(__half2*)&Es[ml * STRD + nl] =
                __floats2half2_rn(c[mi][ni][0], c[mi][ni][1]);
            *(__half2*)&Es[(ml + 8) * STRD + nl] =
                __floats2half2_rn(c[mi][ni][2], c[mi][ni][3]);
        }
    __syncthreads();
#pragma unroll
    for (int i = 0; i < 2; i++) {
        int idx = tid + i * 256;
        int row = idx >> 3;
        int c8  = (idx & 7) * 8;
        uint4 v = *(const uint4*)&Es[row * STRD + c8];
        *(uint4*)&Sb[(size_t)(qt + row) * TK_ + kt + c8] = v;
    }
}

// ---------------------------------------------------------------------------
// Kernel B: P(fp16) = exp(mask((S + Q·pos_k)/8)); emits partial rowsums.
// Epilogue: stage accum to smem, coalesced S-read/exp/P-write (256B rows),
// 16-lane segmented rowsum.
// ---------------------------------------------------------------------------
__device__ __forceinline__ int bswz(int n, int c) {
    return n * 64 + ((((c >> 2) ^ (n & 7)) << 2) | (c & 3));
}
#define CSTR 132

extern "C" __global__ void __launch_bounds__(256)
posk_kernel(const float* __restrict__ PK, const int* __restrict__ VL)
{
    const int q  = blockIdx.y;
    const int kt = blockIdx.x * 128;

    __shared__ __nv_bfloat16 Ah[32][STRD], Al[32][STRD];
    __shared__ float Bs[128 * 64];        // pos_k fp32 swizzled; reused as Cs
    __shared__ float rsum2[32];
    __shared__ int vls[B_];

    const int tid = threadIdx.x;
    {
        int row = tid >> 3;
        int c8  = (tid & 7) * 8;
        cp16(&Ah[row][c8], g_Qh + ((size_t)row * TQ_ + q) * D_ + c8);
        cp16(&Al[row][c8], g_Ql + ((size_t)row * TQ_ + q) * D_ + c8);
    }
    {
        const float* PKq = PK + ((size_t)q * TK_ + kt) * D_;
#pragma unroll
        for (int i = 0; i < 8; i++) {
            int idx = tid + i * 256;
            int row = idx >> 4;
            int c4  = idx & 15;
            cp16(&Bs[row * 64 + ((c4 ^ (row & 7)) << 2)], PKq + row * 64 + c4 * 4);
        }
    }
    CP_COMMIT();
    if (tid < B_) vls[tid] = VL[tid];
    CP_WAIT0();
    __syncthreads();

    const int wid = tid >> 5, lane = tid & 31;
    const int g = lane >> 2, tg = lane & 3;
    const int wn = wid * 16;

    float c[2][2][4] = {};

#pragma unroll
    for (int k0 = 0; k0 < 64; k0 += 16) {
        u32 ah[2][4], al[2][4], bh[2][2], bl[2][2];
#pragma unroll
        for (int mi = 0; mi < 2; mi++) {
            const __nv_bfloat16* ph = &Ah[mi * 16 + g][k0 + 2 * tg];
            ah[mi][0] = *(const u32*)(ph);
            ah[mi][1] = *(const u32*)(ph + 8 * STRD);
            ah[mi][2] = *(const u32*)(ph + 8);
            ah[mi][3] = *(const u32*)(ph + 8 * STRD + 8);
            const __nv_bfloat16* pl = &Al[mi * 16 + g][k0 + 2 * tg];
            al[mi][0] = *(const u32*)(pl);
            al[mi][1] = *(const u32*)(pl + 8 * STRD);
            al[mi][2] = *(const u32*)(pl + 8);
            al[mi][3] = *(const u32*)(pl + 8 * STRD + 8);
        }
#pragma unroll
        for (int ni = 0; ni < 2; ni++) {
            const int n = wn + ni * 8 + g;
            float2 v0 = *(const float2*)&Bs[bswz(n, k0 + 2 * tg)];
            split2(v0.x, v0.y, bh[ni][0], bl[ni][0]);
            float2 v1 = *(const float2*)&Bs[bswz(n, k0 + 2 * tg + 8)];
            split2(v1.x, v1.y, bh[ni][1], bl[ni][1]);
        }
#pragma unroll
        for (int mi = 0; mi < 2; mi++)
#pragma unroll
            for (int ni = 0; ni < 2; ni++) {
                mma_bf16(c[mi][ni], ah[mi][0], ah[mi][1], ah[mi][2], ah[mi][3],
                         bh[ni][0], bh[ni][1]);
                mma_bf16(c[mi][ni], al[mi][0], al[mi][1], al[mi][2], al[mi][3],
                         bh[ni][0], bh[ni][1]);
                mma_bf16(c[mi][ni], ah[mi][0], ah[mi][1], ah[mi][2], ah[mi][3],
                         bl[ni][0], bl[ni][1]);
            }
    }

    // stage accumulators into Cs (reuses Bs)
    __syncthreads();
    float* Cs = Bs;   // [32][CSTR]
#pragma unroll
    for (int mi = 0; mi < 2; mi++)
#pragma unroll
        for (int ni = 0; ni < 2; ni++) {
            const int b0  = mi * 16 + g;
            const int col = wn + ni * 8 + 2 * tg;
            *(float2*)&Cs[b0 * CSTR + col] =
                make_float2(c[mi][ni][0], c[mi][ni][1]);
            *(float2*)&Cs[(b0 + 8) * CSTR + col] =
                make_float2(c[mi][ni][2], c[mi][ni][3]);
        }
    __syncthreads();

    // coalesced S-read / exp / P-write, 256B per row; segmented rowsum
#pragma unroll
    for (int i = 0; i < 2; i++) {
        int idx = tid + i * 256;
        int row = idx >> 4;
        int c8  = (idx & 15) * 8;
        uint4 sv = *(const uint4*)&g_S[((size_t)row * TQ_ + q) * TK_ + kt + c8];
        const int vl = vls[row];
        uint4 out;
        float sum8 = 0.f;
#pragma unroll
        for (int j = 0; j < 4; j++) {
            u32 sraw = ((const u32*)&sv)[j];
            float2 s = __half22float2(*(__half2*)&sraw);
            float cva = Cs[row * CSTR + c8 + 2 * j];
            float cvb = Cs[row * CSTR + c8 + 2 * j + 1];
            int col = kt + c8 + 2 * j;
            float e0 = (col     < vl) ? __expf((s.x + cva) * 0.125f) : 0.f;
            float e1 = (col + 1 < vl) ? __expf((s.y + cvb) * 0.125f) : 0.f;
            __half2 hp = __floats2half2_rn(e0, e1);
            ((u32*)&out)[j] = *(u32*)&hp;
            float2 er = __half22float2(hp);
            sum8 += er.x + er.y;
        }
        *(uint4*)&g_P[((size_t)row * TQ_ + q) * TK_ + kt + c8] = out;
        float v = sum8;
        v += __shfl_xor_sync(0xffffffffu, v, 1);
        v += __shfl_xor_sync(0xffffffffu, v, 2);
        v += __shfl_xor_sync(0xffffffffu, v, 4);
        v += __shfl_xor_sync(0xffffffffu, v, 8);
        if ((lane & 15) == 0) rsum2[row] = v;
    }
    __syncthreads();
    if (tid < 32)
        g_psum[((size_t)tid * TQ_ + q) * 8 + blockIdx.x] = rsum2[tid];
}

// ---------------------------------------------------------------------------
// Kernel C: O = (1/sum) * P(fp16) · V. grid (16,32). f16 MMA.
// 3-stage cp.async pipeline (R9-measured best for pv); dynamic smem.
// ---------------------------------------------------------------------------
#define PV_AH_BYTES (3 * 64 * STRD * 2)
#define PV_VS_BYTES (3 * 64 * VSTR * 4)
#define PV_SMEM     (PV_AH_BYTES + PV_VS_BYTES + 64 * 4)

extern "C" __global__ void __launch_bounds__(256)
pv_kernel(const float* __restrict__ V, float* __restrict__ Out)
{
    extern __shared__ char dynbuf[];
    __half* AhB  = (__half*)dynbuf;                       // [3][64][STRD]
    float*  VsB  = (float*)(dynbuf + PV_AH_BYTES);        // [3][64][VSTR]
    float*  invs = (float*)(dynbuf + PV_AH_BYTES + PV_VS_BYTES);

    const int bz = blockIdx.y;
    const int qt = blockIdx.x * 64;
    const float* Vb = V + (size_t)bz * TK_ * D_;
    const __half* Pb = g_P + (size_t)bz * TQ_ * TK_;

    const int tid = threadIdx.x;
    if (tid < 64) {
        const float* ps = &g_psum[((size_t)bz * TQ_ + qt + tid) * 8];
        float4 a = *(const float4*)ps;
        float4 b = *(const float4*)(ps + 4);
        invs[tid] = 1.0f / (((a.x + a.y) + (a.z + a.w)) + ((b.x + b.y) + (b.z + b.w)));
    }

    auto load_stage = [&](int s, int kt) {
        __half* A = AhB + s * 64 * STRD;
        float*  Vt = VsB + s * 64 * VSTR;
#pragma unroll
        for (int i = 0; i < 2; i++) {          // P: 512 x 16B
            int idx = tid + i * 256;
            int r  = idx >> 3;
            int kc = (idx & 7) * 8;
            cp16(A + r * STRD + kc, Pb + (size_t)(qt + r) * TK_ + kt + kc);
        }
#pragma unroll
        for (int i = 0; i < 4; i++) {          // V: 1024 x 16B
            int idx = tid + i * 256;
            int k  = idx >> 4;
            int dc = (idx & 15) * 4;
            cp16(Vt + k * VSTR + dc, Vb + (size_t)(kt + k) * D_ + dc);
        }
        CP_COMMIT();
    };

    const int wid = tid >> 5, lane = tid & 31;
    const int g = lane >> 2, tg = lane & 3;
    const int wm = (wid >> 2) * 32;
    const int wn = (wid & 3) * 16;

    float c[2][2][4] = {};

    load_stage(0, 0);
    load_stage(1, 64);
    for (int ci = 0; ci < 16; ci++) {
        if (ci == 15) { CP_WAIT0(); } else { CP_WAIT1(); }
        __syncthreads();
        if (ci + 2 < 16) load_stage((ci + 2) % 3, (ci + 2) * 64);

        const int s = ci % 3;
        const __half* A = AhB + s * 64 * STRD;
        const float*  Vt = VsB + s * 64 * VSTR;
#pragma unroll
        for (int k0 = 0; k0 < 64; k0 += 16) {
            u32 a[2][4], bh[2][2], bl[2][2];
#pragma unroll
            for (int mi = 0; mi < 2; mi++) {
                const __half* ph = A + (wm + mi * 16 + g) * STRD + k0 + 2 * tg;
                a[mi][0] = *(const u32*)(ph);
                a[mi][1] = *(const u32*)(ph + 8 * STRD);
                a[mi][2] = *(const u32*)(ph + 8);
                a[mi][3] = *(const u32*)(ph + 8 * STRD + 8);
            }
#pragma unroll
            for (int ni = 0; ni < 2; ni++) {
                const int n = wn + ni * 8 + g;
                const int kb = k0 + 2 * tg;
                split2h(Vt[kb * VSTR + n],       Vt[(kb + 1) * VSTR + n], bh[ni][0], bl[ni][0]);
                split2h(Vt[(kb + 8) * VSTR + n], Vt[(kb + 9) * VSTR + n], bh[ni][1], bl[ni][1]);
            }
#pragma unroll
            for (int mi = 0; mi < 2; mi++)
#pragma unroll
                for (int ni = 0; ni < 2; ni++) {
                    mma_f16(c[mi][ni], a[mi][0], a[mi][1], a[mi][2], a[mi][3],
                            bh[ni][0], bh[ni][1]);
                    mma_f16(c[mi][ni], a[mi][0], a[mi][1], a[mi][2], a[mi][3],
                            bl[ni][0], bl[ni][1]);
                }
        }
    }

#pragma unroll
    for (int mi = 0; mi < 2; mi++)
#pragma unroll
        for (int ni = 0; ni < 2; ni++) {
            int m = wm + mi * 16 + g;
            int n = wn + ni * 8 + 2 * tg;
            float inv0 = invs[m], inv1 = invs[m + 8];
            float* d0 = Out + ((size_t)bz * TQ_ + qt + m) * D_ + n;
            *(float2*)d0 = make_float2(c[mi][ni][0] * inv0, c[mi][ni][1] * inv0);
            float* d1 = Out + ((size_t)bz * TQ_ + qt + m + 8) * D_ + n;
            *(float2*)d1 = make_float2(c[mi][ni][2] * inv1, c[mi][ni][3] * inv1);
        }
}

// ---------------------------------------------------------------------------
// Kernel D: O += (1/sum) * P(fp16) · pos_v[q]. grid (1024). f16 MMA.
// 2-stage cp.async pipeline (measured best); static smem.
// ---------------------------------------------------------------------------
extern "C" __global__ void __launch_bounds__(256)
posv_kernel(const float* __restrict__ PV, float* __restrict__ Out)
{
    const int q = blockIdx.x;

    __shared__ __half Ahs[2][32][STRD];   // P chunks fp16
    __shared__ float  PVs[2][64][VSTR];   // pos_v chunks fp32 [k][d]
    __shared__ float  invs[B_];

    const int tid = threadIdx.x;
    if (tid < B_) {
        const float* ps = &g_psum[((size_t)tid * TQ_ + q) * 8];
        float4 a = *(const float4*)ps;
        float4 b = *(const float4*)(ps + 4);
        invs[tid] = 1.0f / (((a.x + a.y) + (a.z + a.w)) + ((b.x + b.y) + (b.z + b.w)));
    }

    auto load_stage = [&](int s, int kt) {
        {
            int bb = tid >> 3;
            int kc = (tid & 7) * 8;
            cp16(&Ahs[s][bb][kc], g_P + ((size_t)bb * TQ_ + q) * TK_ + kt + kc);
        }
        const float* PVq = PV + ((size_t)q * TK_ + kt) * D_;
#pragma unroll
        for (int i = 0; i < 4; i++) {
            int idx = tid + i * 256;
            int k  = idx >> 4;
            int dc = (idx & 15) * 4;
            cp16(&PVs[s][k][dc], PVq + (size_t)k * D_ + dc);
        }
        CP_COMMIT();
    };

    const int wid = tid >> 5, lane = tid & 31;
    const int g = lane >> 2, tg = lane & 3;
    const int wn = wid * 8;

    float c[2][4] = {};

    load_stage(0, 0);
    for (int ci = 0; ci < 16; ci++) {
        const int s = ci & 1;
        if (ci < 15) { load_stage(s ^ 1, (ci + 1) * 64); CP_WAIT1(); }
        else         { CP_WAIT0(); }
        __syncthreads();

#pragma unroll
        for (int k0 = 0; k0 < 64; k0 += 16) {
            u32 a[2][4], bh[2], bl[2];
#pragma unroll
            for (int mi = 0; mi < 2; mi++) {
                const __half* ph = &Ahs[s][mi * 16 + g][k0 + 2 * tg];
                a[mi][0] = *(const u32*)(ph);
                a[mi][1] = *(const u32*)(ph + 8 * STRD);
                a[mi][2] = *(const u32*)(ph + 8);
                a[mi][3] = *(const u32*)(ph + 8 * STRD + 8);
            }
            {
                const int n = wn + g;
                const int kb = k0 + 2 * tg;
                split2h(PVs[s][kb][n],     PVs[s][kb + 1][n], bh[0], bl[0]);
                split2h(PVs[s][kb + 8][n], PVs[s][kb + 9][n], bh[1], bl[1]);
            }
#pragma unroll
            for (int mi = 0; mi < 2; mi++) {
                mma_f16(c[mi], a[mi][0], a[mi][1], a[mi][2], a[mi][3], bh[0], bh[1]);
                mma_f16(c[mi], a[mi][0], a[mi][1], a[mi][2], a[mi][3], bl[0], bl[1]);
            }
        }
        __syncthreads();
    }

#pragma unroll
    for (int mi = 0; mi < 2; mi++) {
        const int b0 = mi * 16 + g;
        const int b1 = b0 + 8;
        const int n  = wn + 2 * tg;
        float* d0 = Out + ((size_t)b0 * TQ_ + q) * D_ + n;
        float2 o0 = *(float2*)d0;
        o0.x += c[mi][0] * invs[b0];
        o0.y += c[mi][1] * invs[b0];
        *(float2*)d0 = o0;
        float* d1 = Out + ((size_t)b1 * TQ_ + q) * D_ + n;
        float2 o1 = *(float2*)d1;
        o1.x += c[mi][2] * invs[b1];
        o1.y += c[mi][3] * invs[b1];
        *(float2*)d1 = o1;
    }
}

// ---------------------------------------------------------------------------
extern "C" void kernel_launch(void* const* d_in, const int* in_sizes, int n_in,
                              void* d_out, int out_size)
{
    const float* Q  = (const float*)d_in[0];
    const float* K  = (const float*)d_in[1];
    const float* V  = (const float*)d_in[2];
    const float* PK = (const float*)d_in[3];
    const float* PV = (const float*)d_in[4];
    const int*   VL = (const int*)d_in[5];
    float* Out = (float*)d_out;

    cudaFuncSetAttribute(pv_kernel, cudaFuncAttributeMaxDynamicSharedMemorySize,
                         PV_SMEM);

    prep_qk_kernel<<<2048, 256>>>(Q, K);
    qk_kernel<<<dim3(TK_ / 64, TQ_ / 64, B_), 256>>>();
    posk_kernel<<<dim3(TK_ / 128, TQ_), 256>>>(PK, VL);
    pv_kernel<<<dim3(TQ_ / 64, B_), 256, PV_SMEM>>>(V, Out);
    posv_kernel<<<TQ_, 256>>>(PV, Out);
}

// round 12
// speedup vs baseline: 1.1509x; 1.0342x over previous
#include <cuda_runtime.h>
#include <cuda_bf16.h>
#include <cuda_fp16.h>
#include <math.h>

typedef unsigned u32;

#define B_  32
#define TQ_ 1024
#define TK_ 1024
#define D_  64
#define STRD 72   // smem row stride in 2B elems (64 data + 8 pad): conflict-free frags
#define VSTR 68   // fp32 tile row stride (conflict-free for split reads)

// scratch: fp16 scores/probs, partial rowsums, precomputed bf16 hi/lo Q,K
static __device__ __half g_S[(size_t)B_ * TQ_ * TK_];
static __device__ __half g_P[(size_t)B_ * TQ_ * TK_];
static __device__ float  g_psum[(size_t)B_ * TQ_ * 8];
static __device__ __nv_bfloat16 g_Qh[(size_t)B_ * TQ_ * D_];
static __device__ __nv_bfloat16 g_Ql[(size_t)B_ * TQ_ * D_];
static __device__ __nv_bfloat16 g_Kh[(size_t)B_ * TK_ * D_];
static __device__ __nv_bfloat16 g_Kl[(size_t)B_ * TK_ * D_];

// ---- mma helpers ----------------------------------------------------------
__device__ __forceinline__ void mma_bf16(float c[4], u32 a0, u32 a1, u32 a2, u32 a3,
                                         u32 b0, u32 b1)
{
    asm volatile(
        "mma.sync.aligned.m16n8k16.row.col.f32.bf16.bf16.f32 "
        "{%0,%1,%2,%3},{%4,%5,%6,%7},{%8,%9},{%0,%1,%2,%3};\n"
        : "+f"(c[0]), "+f"(c[1]), "+f"(c[2]), "+f"(c[3])
        : "r"(a0), "r"(a1), "r"(a2), "r"(a3), "r"(b0), "r"(b1));
}
__device__ __forceinline__ void mma_f16(float c[4], u32 a0, u32 a1, u32 a2, u32 a3,
                                        u32 b0, u32 b1)
{
    asm volatile(
        "mma.sync.aligned.m16n8k16.row.col.f32.f16.f16.f32 "
        "{%0,%1,%2,%3},{%4,%5,%6,%7},{%8,%9},{%0,%1,%2,%3};\n"
        : "+f"(c[0]), "+f"(c[1]), "+f"(c[2]), "+f"(c[3])
        : "r"(a0), "r"(a1), "r"(a2), "r"(a3), "r"(b0), "r"(b1));
}

__device__ __forceinline__ u32 cvt2bf(float hi, float lo) {
    u32 r;
    asm("cvt.rn.bf16x2.f32 %0,%1,%2;" : "=r"(r) : "f"(hi), "f"(lo));
    return r;
}
// bf16 hi/lo split (x0 -> low half, x1 -> high half)
__device__ __forceinline__ void split2(float x0, float x1, u32& h, u32& l) {
    h = cvt2bf(x1, x0);
    float h0 = __uint_as_float(h << 16);
    float h1 = __uint_as_float(h & 0xffff0000u);
    l = cvt2bf(x1 - h1, x0 - h0);
}
// fp16 hi/lo split
__device__ __forceinline__ void split2h(float x0, float x1, u32& h, u32& l) {
    __half2 hh = __floats2half2_rn(x0, x1);
    h = *(u32*)&hh;
    float2 hf = __half22float2(hh);
    __half2 ll = __floats2half2_rn(x0 - hf.x, x1 - hf.y);
    l = *(u32*)&ll;
}

// ---- cp.async helpers -----------------------------------------------------
__device__ __forceinline__ void cp16(void* dst_smem, const void* src) {
    u32 d = (u32)__cvta_generic_to_shared(dst_smem);
    asm volatile("cp.async.cg.shared.global [%0], [%1], 16;\n" :: "r"(d), "l"(src));
}
#define CP_COMMIT() asm volatile("cp.async.commit_group;\n" ::)
#define CP_WAIT1()  asm volatile("cp.async.wait_group 1;\n" ::)
#define CP_WAIT0()  asm volatile("cp.async.wait_group 0;\n" ::)

// ---------------------------------------------------------------------------
// Kernel P0: precompute bf16 hi/lo for Q and K (row-major, same layout)
// ---------------------------------------------------------------------------
extern "C" __global__ void __launch_bounds__(256)
prep_qk_kernel(const float* __restrict__ Q, const float* __restrict__ K)
{
    size_t idx = (size_t)blockIdx.x * 256 + threadIdx.x;
    float4 v = ((const float4*)Q)[idx];
    u32 h0, l0, h1, l1;
    split2(v.x, v.y, h0, l0); split2(v.z, v.w, h1, l1);
    ((uint2*)g_Qh)[idx] = make_uint2(h0, h1);
    ((uint2*)g_Ql)[idx] = make_uint2(l0, l1);
    float4 w = ((const float4*)K)[idx];
    split2(w.x, w.y, h0, l0); split2(w.z, w.w, h1, l1);
    ((uint2*)g_Kh)[idx] = make_uint2(h0, h1);
    ((uint2*)g_Kl)[idx] = make_uint2(l0, l1);
}

// ---------------------------------------------------------------------------
// Kernel A: S[b,q,k] = Q[b,q,:]·K[b,k,:] (unscaled, fp16 out). bf16x3 MMA.
// Block tile 128(q) x 64(k); warps 4(m) x 2(n); dynamic smem (55.3 KB).
// ---------------------------------------------------------------------------
#define QK_A_H   (128 * STRD)                  // halves per A array
#define QK_B_H   (64 * STRD)
#define QK_SMEM  ((2 * QK_A_H + 2 * QK_B_H) * 2)

extern "C" __global__ void __launch_bounds__(256)
qk_kernel()
{
    extern __shared__ char dynq[];
    __half* Ah = (__half*)dynq;                 // [128][STRD] (bf16 bits)
    __half* Al = Ah + QK_A_H;
    __half* Bh = Al + QK_A_H;                   // [64][STRD]
    __half* Bl = Bh + QK_B_H;

    const int bz = blockIdx.z;
    const int qt = blockIdx.y * 128;
    const int kt = blockIdx.x * 64;
    __half* Sb = g_S + (size_t)bz * TQ_ * TK_;

    const int tid = threadIdx.x;
    {
        const __nv_bfloat16* qh = g_Qh + ((size_t)bz * TQ_ + qt) * D_;
        const __nv_bfloat16* ql = g_Ql + ((size_t)bz * TQ_ + qt) * D_;
#pragma unroll
        for (int i = 0; i < 2; i++) {           // 512 chunks over 128 rows x 4
            int idx = tid + i * 256;
            int row = idx >> 2;
            int c8  = (idx & 3) * 16;
            cp16(Ah + row * STRD + c8,     qh + row * D_ + c8);
            cp16(Ah + row * STRD + c8 + 8, qh + row * D_ + c8 + 8);
            cp16(Al + row * STRD + c8,     ql + row * D_ + c8);
            cp16(Al + row * STRD + c8 + 8, ql + row * D_ + c8 + 8);
        }
        const __nv_bfloat16* kh = g_Kh + ((size_t)bz * TK_ + kt) * D_;
        const __nv_bfloat16* kl = g_Kl + ((size_t)bz * TK_ + kt) * D_;
        {                                       // 256 chunks over 64 rows x 4
            int row = tid >> 2;
            int c8  = (tid & 3) * 16;
            cp16(Bh + row * STRD + c8,     kh + row * D_ + c8);
            cp16(Bh + row * STRD + c8 + 8, kh + row * D_ + c8 + 8);
            cp16(Bl + row * STRD + c8,     kl + row * D_ + c8);
            cp16(Bl + row * STRD + c8 + 8, kl + row * D_ + c8 + 8);
        }
    }
    CP_COMMIT();
    CP_WAIT0();
    __syncthreads();

    const int wid = tid >> 5, lane = tid & 31;
    const int g = lane >> 2, tg = lane & 3;
    const int wm = (wid >> 1) * 32;             // 0,32,64,96
    const int wn = (wid & 1) * 32;              // 0,32

    float c[2][4][4] = {};

#pragma unroll
    for (int k0 = 0; k0 < 64; k0 += 16) {
        u32 ah[2][4], al[2][4], bh[4][2], bl[4][2];
#pragma unroll
        for (int mi = 0; mi < 2; mi++) {
            const __half* ph = Ah + (wm + mi * 16 + g) * STRD + k0 + 2 * tg;
            ah[mi][0] = *(const u32*)(ph);
            ah[mi][1] = *(const u32*)(ph + 8 * STRD);
            ah[mi][2] = *(const u32*)(ph + 8);
            ah[mi][3] = *(const u32*)(ph + 8 * STRD + 8);
            const __half* pl = Al + (wm + mi * 16 + g) * STRD + k0 + 2 * tg;
            al[mi][0] = *(const u32*)(pl);
            al[mi][1] = *(const u32*)(pl + 8 * STRD);
            al[mi][2] = *(const u32*)(pl + 8);
            al[mi][3] = *(const u32*)(pl + 8 * STRD + 8);
        }
#pragma unroll
        for (int ni = 0; ni < 4; ni++) {
            const __half* ph = Bh + (wn + ni * 8 + g) * STRD + k0 + 2 * tg;
            bh[ni][0] = *(const u32*)(ph);
            bh[ni][1] = *(const u32*)(ph + 8);
            const __half* pl = Bl + (wn + ni * 8 + g) * STRD + k0 + 2 * tg;
            bl[ni][0] = *(const u32*)(pl);
            bl[ni][1] = *(const u32*)(pl + 8);
        }
#pragma unroll
        for (int mi = 0; mi < 2; mi++)
#pragma unroll
            for (int ni = 0; ni < 4; ni++) {
                mma_bf16(c[mi][ni], ah[mi][0], ah[mi][1], ah[mi][2], ah[mi][3],
                         bh[ni][0], bh[ni][1]);
                mma_bf16(c[mi][ni], al[mi][0], al[mi][1], al[mi][2], al[mi][3],
                         bh[ni][0], bh[ni][1]);
                mma_bf16(c[mi][ni], ah[mi][0], ah[mi][1], ah[mi][2], ah[mi][3],
                         bl[ni][0], bl[ni][1]);
            }
    }

    // stage to smem (reuse Ah, 128 rows), then coalesced 128B-row stores
    __syncthreads();
    __half* Es = Ah;   // [128][STRD]
#pragma unroll
    for (int mi = 0; mi < 2; mi++)
#pragma unroll
        for (int ni = 0; ni < 4; ni++) {
            int ml = wm + mi * 16 + g;
            int nl = wn + ni * 8 + 2 * tg;
            *(__half2*)&Es[ml * STRD + nl] =
                __floats2half2_rn(c[mi][ni][0], c[mi][ni][1]);
            *(__half2*)&Es[(ml + 8) * STRD + nl] =
                __floats2half2_rn(c[mi][ni][2], c[mi][ni][3]);
        }
    __syncthreads();
#pragma unroll
    for (int i = 0; i < 4; i++) {
        int idx = tid + i * 256;
        int row = idx >> 3;
        int c8  = (idx & 7) * 8;
        uint4 v = *(const uint4*)&Es[row * STRD + c8];
        *(uint4*)&Sb[(size_t)(qt + row) * TK_ + kt + c8] = v;
    }
}

// ---------------------------------------------------------------------------
// Kernel B: P(fp16) = exp(mask((S + Q·pos_k)/8)); emits partial rowsums.
// ---------------------------------------------------------------------------
__device__ __forceinline__ int bswz(int n, int c) {
    return n * 64 + ((((c >> 2) ^ (n & 7)) << 2) | (c & 3));
}
#define CSTR 132

extern "C" __global__ void __launch_bounds__(256)
posk_kernel(const float* __restrict__ PK, const int* __restrict__ VL)
{
    const int q  = blockIdx.y;
    const int kt = blockIdx.x * 128;

    __shared__ __nv_bfloat16 Ah[32][STRD], Al[32][STRD];
    __shared__ float Bs[128 * 64];        // pos_k fp32 swizzled; reused as Cs
    __shared__ float rsum2[32];
    __shared__ int vls[B_];

    const int tid = threadIdx.x;
    {
        int row = tid >> 3;
        int c8  = (tid & 7) * 8;
        cp16(&Ah[row][c8], g_Qh + ((size_t)row * TQ_ + q) * D_ + c8);
        cp16(&Al[row][c8], g_Ql + ((size_t)row * TQ_ + q) * D_ + c8);
    }
    {
        const float* PKq = PK + ((size_t)q * TK_ + kt) * D_;
#pragma unroll
        for (int i = 0; i < 8; i++) {
            int idx = tid + i * 256;
            int row = idx >> 4;
            int c4  = idx & 15;
            cp16(&Bs[row * 64 + ((c4 ^ (row & 7)) << 2)], PKq + row * 64 + c4 * 4);
        }
    }
    CP_COMMIT();
    if (tid < B_) vls[tid] = VL[tid];
    CP_WAIT0();
    __syncthreads();

    const int wid = tid >> 5, lane = tid & 31;
    const int g = lane >> 2, tg = lane & 3;
    const int wn = wid * 16;

    float c[2][2][4] = {};

#pragma unroll
    for (int k0 = 0; k0 < 64; k0 += 16) {
        u32 ah[2][4], al[2][4], bh[2][2], bl[2][2];
#pragma unroll
        for (int mi = 0; mi < 2; mi++) {
            const __nv_bfloat16* ph = &Ah[mi * 16 + g][k0 + 2 * tg];
            ah[mi][0] = *(const u32*)(ph);
            ah[mi][1] = *(const u32*)(ph + 8 * STRD);
            ah[mi][2] = *(const u32*)(ph + 8);
            ah[mi][3] = *(const u32*)(ph + 8 * STRD + 8);
            const __nv_bfloat16* pl = &Al[mi * 16 + g][k0 + 2 * tg];
            al[mi][0] = *(const u32*)(pl);
            al[mi][1] = *(const u32*)(pl + 8 * STRD);
            al[mi][2] = *(const u32*)(pl + 8);
            al[mi][3] = *(const u32*)(pl + 8 * STRD + 8);
        }
#pragma unroll
        for (int ni = 0; ni < 2; ni++) {
            const int n = wn + ni * 8 + g;
            float2 v0 = *(const float2*)&Bs[bswz(n, k0 + 2 * tg)];
            split2(v0.x, v0.y, bh[ni][0], bl[ni][0]);
            float2 v1 = *(const float2*)&Bs[bswz(n, k0 + 2 * tg + 8)];
            split2(v1.x, v1.y, bh[ni][1], bl[ni][1]);
        }
#pragma unroll
        for (int mi = 0; mi < 2; mi++)
#pragma unroll
            for (int ni = 0; ni < 2; ni++) {
                mma_bf16(c[mi][ni], ah[mi][0], ah[mi][1], ah[mi][2], ah[mi][3],
                         bh[ni][0], bh[ni][1]);
                mma_bf16(c[mi][ni], al[mi][0], al[mi][1], al[mi][2], al[mi][3],
                         bh[ni][0], bh[ni][1]);
                mma_bf16(c[mi][ni], ah[mi][0], ah[mi][1], ah[mi][2], ah[mi][3],
                         bl[ni][0], bl[ni][1]);
            }
    }

    // stage accumulators into Cs (reuses Bs)
    __syncthreads();
    float* Cs = Bs;   // [32][CSTR]
#pragma unroll
    for (int mi = 0; mi < 2; mi++)
#pragma unroll
        for (int ni = 0; ni < 2; ni++) {
            const int b0  = mi * 16 + g;
            const int col = wn + ni * 8 + 2 * tg;
            *(float2*)&Cs[b0 * CSTR + col] =
                make_float2(c[mi][ni][0], c[mi][ni][1]);
            *(float2*)&Cs[(b0 + 8) * CSTR + col] =
                make_float2(c[mi][ni][2], c[mi][ni][3]);
        }
    __syncthreads();

    // coalesced S-read / exp / P-write, 256B per row; segmented rowsum
#pragma unroll
    for (int i = 0; i < 2; i++) {
        int idx = tid + i * 256;
        int row = idx >> 4;
        int c8  = (idx & 15) * 8;
        uint4 sv = *(const uint4*)&g_S[((size_t)row * TQ_ + q) * TK_ + kt + c8];
        const int vl = vls[row];
        uint4 out;
        float sum8 = 0.f;
#pragma unroll
        for (int j = 0; j < 4; j++) {
            u32 sraw = ((const u32*)&sv)[j];
            float2 s = __half22float2(*(__half2*)&sraw);
            float cva = Cs[row * CSTR + c8 + 2 * j];
            float cvb = Cs[row * CSTR + c8 + 2 * j + 1];
            int col = kt + c8 + 2 * j;
            float e0 = (col     < vl) ? __expf((s.x + cva) * 0.125f) : 0.f;
            float e1 = (col + 1 < vl) ? __expf((s.y + cvb) * 0.125f) : 0.f;
            __half2 hp = __floats2half2_rn(e0, e1);
            ((u32*)&out)[j] = *(u32*)&hp;
            float2 er = __half22float2(hp);
            sum8 += er.x + er.y;
        }
        *(uint4*)&g_P[((size_t)row * TQ_ + q) * TK_ + kt + c8] = out;
        float v = sum8;
        v += __shfl_xor_sync(0xffffffffu, v, 1);
        v += __shfl_xor_sync(0xffffffffu, v, 2);
        v += __shfl_xor_sync(0xffffffffu, v, 4);
        v += __shfl_xor_sync(0xffffffffu, v, 8);
        if ((lane & 15) == 0) rsum2[row] = v;
    }
    __syncthreads();
    if (tid < 32)
        g_psum[((size_t)tid * TQ_ + q) * 8 + blockIdx.x] = rsum2[tid];
}

// ---------------------------------------------------------------------------
// Kernel C: O = (1/sum) * P(fp16) · V. grid (16,32). f16 MMA.
// 2-stage cp.async pipeline (occupancy-optimized); dynamic smem 53.2 KB.
// ---------------------------------------------------------------------------
#define PV_AH_BYTES (2 * 64 * STRD * 2)
#define PV_VS_BYTES (2 * 64 * VSTR * 4)
#define PV_SMEM     (PV_AH_BYTES + PV_VS_BYTES + 64 * 4)

extern "C" __global__ void __launch_bounds__(256)
pv_kernel(const float* __restrict__ V, float* __restrict__ Out)
{
    extern __shared__ char dynbuf[];
    __half* AhB  = (__half*)dynbuf;                       // [2][64][STRD]
    float*  VsB  = (float*)(dynbuf + PV_AH_BYTES);        // [2][64][VSTR]
    float*  invs = (float*)(dynbuf + PV_AH_BYTES + PV_VS_BYTES);

    const int bz = blockIdx.y;
    const int qt = blockIdx.x * 64;
    const float* Vb = V + (size_t)bz * TK_ * D_;
    const __half* Pb = g_P + (size_t)bz * TQ_ * TK_;

    const int tid = threadIdx.x;
    if (tid < 64) {
        const float* ps = &g_psum[((size_t)bz * TQ_ + qt + tid) * 8];
        float4 a = *(const float4*)ps;
        float4 b = *(const float4*)(ps + 4);
        invs[tid] = 1.0f / (((a.x + a.y) + (a.z + a.w)) + ((b.x + b.y) + (b.z + b.w)));
    }

    auto load_stage = [&](int s, int kt) {
        __half* A = AhB + s * 64 * STRD;
        float*  Vt = VsB + s * 64 * VSTR;
#pragma unroll
        for (int i = 0; i < 2; i++) {          // P: 512 x 16B
            int idx = tid + i * 256;
            int r  = idx >> 3;
            int kc = (idx & 7) * 8;
            cp16(A + r * STRD + kc, Pb + (size_t)(qt + r) * TK_ + kt + kc);
        }
#pragma unroll
        for (int i = 0; i < 4; i++) {          // V: 1024 x 16B
            int idx = tid + i * 256;
            int k  = idx >> 4;
            int dc = (idx & 15) * 4;
            cp16(Vt + k * VSTR + dc, Vb + (size_t)(kt + k) * D_ + dc);
        }
        CP_COMMIT();
    };

    const int wid = tid >> 5, lane = tid & 31;
    const int g = lane >> 2, tg = lane & 3;
    const int wm = (wid >> 2) * 32;
    const int wn = (wid & 3) * 16;

    float c[2][2][4] = {};

    load_stage(0, 0);
    for (int ci = 0; ci < 16; ci++) {
        const int s = ci & 1;
        if (ci < 15) { load_stage(s ^ 1, (ci + 1) * 64); CP_WAIT1(); }
        else         { CP_WAIT0(); }
        __syncthreads();

        const __half* A = AhB + s * 64 * STRD;
        const float*  Vt = VsB + s * 64 * VSTR;
#pragma unroll
        for (int k0 = 0; k0 < 64; k0 += 16) {
            u32 a[2][4], bh[2][2], bl[2][2];
#pragma unroll
            for (int mi = 0; mi < 2; mi++) {
                const __half* ph = A + (wm + mi * 16 + g) * STRD + k0 + 2 * tg;
                a[mi][0] = *(const u32*)(ph);
                a[mi][1] = *(const u32*)(ph + 8 * STRD);
                a[mi][2] = *(const u32*)(ph + 8);
                a[mi][3] = *(const u32*)(ph + 8 * STRD + 8);
            }
#pragma unroll
            for (int ni = 0; ni < 2; ni++) {
                const int n = wn + ni * 8 + g;
                const int kb = k0 + 2 * tg;
                split2h(Vt[kb * VSTR + n],       Vt[(kb + 1) * VSTR + n], bh[ni][0], bl[ni][0]);
                split2h(Vt[(kb + 8) * VSTR + n], Vt[(kb + 9) * VSTR + n], bh[ni][1], bl[ni][1]);
            }
#pragma unroll
            for (int mi = 0; mi < 2; mi++)
#pragma unroll
                for (int ni = 0; ni < 2; ni++) {
                    mma_f16(c[mi][ni], a[mi][0], a[mi][1], a[mi][2], a[mi][3],
                            bh[ni][0], bh[ni][1]);
                    mma_f16(c[mi][ni], a[mi][0], a[mi][1], a[mi][2], a[mi][3],
                            bl[ni][0], bl[ni][1]);
                }
        }
        __syncthreads();
    }

#pragma unroll
    for (int mi = 0; mi < 2; mi++)
#pragma unroll
        for (int ni = 0; ni < 2; ni++) {
            int m = wm + mi * 16 + g;
            int n = wn + ni * 8 + 2 * tg;
            float inv0 = invs[m], inv1 = invs[m + 8];
            float* d0 = Out + ((size_t)bz * TQ_ + qt + m) * D_ + n;
            *(float2*)d0 = make_float2(c[mi][ni][0] * inv0, c[mi][ni][1] * inv0);
            float* d1 = Out + ((size_t)bz * TQ_ + qt + m + 8) * D_ + n;
            *(float2*)d1 = make_float2(c[mi][ni][2] * inv1, c[mi][ni][3] * inv1);
        }
}

// ---------------------------------------------------------------------------
// Kernel D: O += (1/sum) * P(fp16) · pos_v[q]. grid (1024). f16 MMA.
// 2-stage cp.async pipeline (measured best); static smem.
// ---------------------------------------------------------------------------
extern "C" __global__ void __launch_bounds__(256)
posv_kernel(const float* __restrict__ PV, float* __restrict__ Out)
{
    const int q = blockIdx.x;

    __shared__ __half Ahs[2][32][STRD];   // P chunks fp16
    __shared__ float  PVs[2][64][VSTR];   // pos_v chunks fp32 [k][d]
    __shared__ float  invs[B_];

    const int tid = threadIdx.x;
    if (tid < B_) {
        const float* ps = &g_psum[((size_t)tid * TQ_ + q) * 8];
        float4 a = *(const float4*)ps;
        float4 b = *(const float4*)(ps + 4);
        invs[tid] = 1.0f / (((a.x + a.y) + (a.z + a.w)) + ((b.x + b.y) + (b.z + b.w)));
    }

    auto load_stage = [&](int s, int kt) {
        {
            int bb = tid >> 3;
            int kc = (tid & 7) * 8;
            cp16(&Ahs[s][bb][kc], g_P + ((size_t)bb * TQ_ + q) * TK_ + kt + kc);
        }
        const float* PVq = PV + ((size_t)q * TK_ + kt) * D_;
#pragma unroll
        for (int i = 0; i < 4; i++) {
            int idx = tid + i * 256;
            int k  = idx >> 4;
            int dc = (idx & 15) * 4;
            cp16(&PVs[s][k][dc], PVq + (size_t)k * D_ + dc);
        }
        CP_COMMIT();
    };

    const int wid = tid >> 5, lane = tid & 31;
    const int g = lane >> 2, tg = lane & 3;
    const int wn = wid * 8;

    float c[2][4] = {};

    load_stage(0, 0);
    for (int ci = 0; ci < 16; ci++) {
        const int s = ci & 1;
        if (ci < 15) { load_stage(s ^ 1, (ci + 1) * 64); CP_WAIT1(); }
        else         { CP_WAIT0(); }
        __syncthreads();

#pragma unroll
        for (int k0 = 0; k0 < 64; k0 += 16) {
            u32 a[2][4], bh[2], bl[2];
#pragma unroll
            for (int mi = 0; mi < 2; mi++) {
                const __half* ph = &Ahs[s][mi * 16 + g][k0 + 2 * tg];
                a[mi][0] = *(const u32*)(ph);
                a[mi][1] = *(const u32*)(ph + 8 * STRD);
                a[mi][2] = *(const u32*)(ph + 8);
                a[mi][3] = *(const u32*)(ph + 8 * STRD + 8);
            }
            {
                const int n = wn + g;
                const int kb = k0 + 2 * tg;
                split2h(PVs[s][kb][n],     PVs[s][kb + 1][n], bh[0], bl[0]);
                split2h(PVs[s][kb + 8][n], PVs[s][kb + 9][n], bh[1], bl[1]);
            }
#pragma unroll
            for (int mi = 0; mi < 2; mi++) {
                mma_f16(c[mi], a[mi][0], a[mi][1], a[mi][2], a[mi][3], bh[0], bh[1]);
                mma_f16(c[mi], a[mi][0], a[mi][1], a[mi][2], a[mi][3], bl[0], bl[1]);
            }
        }
        __syncthreads();
    }

#pragma unroll
    for (int mi = 0; mi < 2; mi++) {
        const int b0 = mi * 16 + g;
        const int b1 = b0 + 8;
        const int n  = wn + 2 * tg;
        float* d0 = Out + ((size_t)b0 * TQ_ + q) * D_ + n;
        float2 o0 = *(float2*)d0;
        o0.x += c[mi][0] * invs[b0];
        o0.y += c[mi][1] * invs[b0];
        *(float2*)d0 = o0;
        float* d1 = Out + ((size_t)b1 * TQ_ + q) * D_ + n;
        float2 o1 = *(float2*)d1;
        o1.x += c[mi][2] * invs[b1];
        o1.y += c[mi][3] * invs[b1];
        *(float2*)d1 = o1;
    }
}

// ---------------------------------------------------------------------------
extern "C" void kernel_launch(void* const* d_in, const int* in_sizes, int n_in,
                              void* d_out, int out_size)
{
    const float* Q  = (const float*)d_in[0];
    const float* K  = (const float*)d_in[1];
    const float* V  = (const float*)d_in[2];
    const float* PK = (const float*)d_in[3];
    const float* PV = (const float*)d_in[4];
    const int*   VL = (const int*)d_in[5];
    float* Out = (float*)d_out;

    cudaFuncSetAttribute(qk_kernel, cudaFuncAttributeMaxDynamicSharedMemorySize,
                         QK_SMEM);
    cudaFuncSetAttribute(pv_kernel, cudaFuncAttributeMaxDynamicSharedMemorySize,
                         PV_SMEM);

    prep_qk_kernel<<<2048, 256>>>(Q, K);
    qk_kernel<<<dim3(TK_ / 64, TQ_ / 128, B_), 256, QK_SMEM>>>();
    posk_kernel<<<dim3(TK_ / 128, TQ_), 256>>>(PK, VL);
    pv_kernel<<<dim3(TQ_ / 64, B_), 256, PV_SMEM>>>(V, Out);
    posv_kernel<<<TQ_, 256>>>(PV, Out);
}

// round 13
// speedup vs baseline: 1.2313x; 1.0698x over previous
#include <cuda_runtime.h>
#include <cuda_bf16.h>
#include <cuda_fp16.h>
#include <math.h>

typedef unsigned u32;

#define B_  32
#define TQ_ 1024
#define TK_ 1024
#define D_  64
#define STRD 72   // smem row stride in 2B elems (64 data + 8 pad): conflict-free frags
#define VSTR 68   // fp32 tile row stride (conflict-free for split reads)

// scratch: fp16 scores/probs, partial rowsums, precomputed bf16 hi/lo Q,K,
// and a separate accumulator for the pos_v contribution (race-free overlap)
static __device__ __half g_S[(size_t)B_ * TQ_ * TK_];
static __device__ __half g_P[(size_t)B_ * TQ_ * TK_];
static __device__ float  g_psum[(size_t)B_ * TQ_ * 8];
static __device__ float  g_O2[(size_t)B_ * TQ_ * D_];
static __device__ __nv_bfloat16 g_Qh[(size_t)B_ * TQ_ * D_];
static __device__ __nv_bfloat16 g_Ql[(size_t)B_ * TQ_ * D_];
static __device__ __nv_bfloat16 g_Kh[(size_t)B_ * TK_ * D_];
static __device__ __nv_bfloat16 g_Kl[(size_t)B_ * TK_ * D_];

// ---- mma helpers ----------------------------------------------------------
__device__ __forceinline__ void mma_bf16(float c[4], u32 a0, u32 a1, u32 a2, u32 a3,
                                         u32 b0, u32 b1)
{
    asm volatile(
        "mma.sync.aligned.m16n8k16.row.col.f32.bf16.bf16.f32 "
        "{%0,%1,%2,%3},{%4,%5,%6,%7},{%8,%9},{%0,%1,%2,%3};\n"
        : "+f"(c[0]), "+f"(c[1]), "+f"(c[2]), "+f"(c[3])
        : "r"(a0), "r"(a1), "r"(a2), "r"(a3), "r"(b0), "r"(b1));
}
__device__ __forceinline__ void mma_f16(float c[4], u32 a0, u32 a1, u32 a2, u32 a3,
                                        u32 b0, u32 b1)
{
    asm volatile(
        "mma.sync.aligned.m16n8k16.row.col.f32.f16.f16.f32 "
        "{%0,%1,%2,%3},{%4,%5,%6,%7},{%8,%9},{%0,%1,%2,%3};\n"
        : "+f"(c[0]), "+f"(c[1]), "+f"(c[2]), "+f"(c[3])
        : "r"(a0), "r"(a1), "r"(a2), "r"(a3), "r"(b0), "r"(b1));
}

__device__ __forceinline__ u32 cvt2bf(float hi, float lo) {
    u32 r;
    asm("cvt.rn.bf16x2.f32 %0,%1,%2;" : "=r"(r) : "f"(hi), "f"(lo));
    return r;
}
// bf16 hi/lo split (x0 -> low half, x1 -> high half)
__device__ __forceinline__ void split2(float x0, float x1, u32& h, u32& l) {
    h = cvt2bf(x1, x0);
    float h0 = __uint_as_float(h << 16);
    float h1 = __uint_as_float(h & 0xffff0000u);
    l = cvt2bf(x1 - h1, x0 - h0);
}
// fp16 hi/lo split
__device__ __forceinline__ void split2h(float x0, float x1, u32& h, u32& l) {
    __half2 hh = __floats2half2_rn(x0, x1);
    h = *(u32*)&hh;
    float2 hf = __half22float2(hh);
    __half2 ll = __floats2half2_rn(x0 - hf.x, x1 - hf.y);
    l = *(u32*)&ll;
}

// ---- cp.async helpers -----------------------------------------------------
__device__ __forceinline__ void cp16(void* dst_smem, const void* src) {
    u32 d = (u32)__cvta_generic_to_shared(dst_smem);
    asm volatile("cp.async.cg.shared.global [%0], [%1], 16;\n" :: "r"(d), "l"(src));
}
#define CP_COMMIT() asm volatile("cp.async.commit_group;\n" ::)
#define CP_WAIT1()  asm volatile("cp.async.wait_group 1;\n" ::)
#define CP_WAIT0()  asm volatile("cp.async.wait_group 0;\n" ::)

// ---------------------------------------------------------------------------
// Kernel P0: precompute bf16 hi/lo for Q and K (row-major, same layout)
// ---------------------------------------------------------------------------
extern "C" __global__ void __launch_bounds__(256)
prep_qk_kernel(const float* __restrict__ Q, const float* __restrict__ K)
{
    size_t idx = (size_t)blockIdx.x * 256 + threadIdx.x;
    float4 v = ((const float4*)Q)[idx];
    u32 h0, l0, h1, l1;
    split2(v.x, v.y, h0, l0); split2(v.z, v.w, h1, l1);
    ((uint2*)g_Qh)[idx] = make_uint2(h0, h1);
    ((uint2*)g_Ql)[idx] = make_uint2(l0, l1);
    float4 w = ((const float4*)K)[idx];
    split2(w.x, w.y, h0, l0); split2(w.z, w.w, h1, l1);
    ((uint2*)g_Kh)[idx] = make_uint2(h0, h1);
    ((uint2*)g_Kl)[idx] = make_uint2(l0, l1);
}

// ---------------------------------------------------------------------------
// Kernel A: S[b,q,k] = Q[b,q,:]·K[b,k,:] (unscaled, fp16 out). bf16x3 MMA.
// Block tile 128(q) x 64(k); warps 4(m) x 2(n); dynamic smem (55.3 KB).
// ---------------------------------------------------------------------------
#define QK_A_H   (128 * STRD)                  // halves per A array
#define QK_B_H   (64 * STRD)
#define QK_SMEM  ((2 * QK_A_H + 2 * QK_B_H) * 2)

extern "C" __global__ void __launch_bounds__(256)
qk_kernel()
{
    extern __shared__ char dynq[];
    __half* Ah = (__half*)dynq;                 // [128][STRD] (bf16 bits)
    __half* Al = Ah + QK_A_H;
    __half* Bh = Al + QK_A_H;                   // [64][STRD]
    __half* Bl = Bh + QK_B_H;

    const int bz = blockIdx.z;
    const int qt = blockIdx.y * 128;
    const int kt = blockIdx.x * 64;
    __half* Sb = g_S + (size_t)bz * TQ_ * TK_;

    const int tid = threadIdx.x;
    {
        const __nv_bfloat16* qh = g_Qh + ((size_t)bz * TQ_ + qt) * D_;
        const __nv_bfloat16* ql = g_Ql + ((size_t)bz * TQ_ + qt) * D_;
#pragma unroll
        for (int i = 0; i < 2; i++) {
            int idx = tid + i * 256;
            int row = idx >> 2;
            int c8  = (idx & 3) * 16;
            cp16(Ah + row * STRD + c8,     qh + row * D_ + c8);
            cp16(Ah + row * STRD + c8 + 8, qh + row * D_ + c8 + 8);
            cp16(Al + row * STRD + c8,     ql + row * D_ + c8);
            cp16(Al + row * STRD + c8 + 8, ql + row * D_ + c8 + 8);
        }
        const __nv_bfloat16* kh = g_Kh + ((size_t)bz * TK_ + kt) * D_;
        const __nv_bfloat16* kl = g_Kl + ((size_t)bz * TK_ + kt) * D_;
        {
            int row = tid >> 2;
            int c8  = (tid & 3) * 16;
            cp16(Bh + row * STRD + c8,     kh + row * D_ + c8);
            cp16(Bh + row * STRD + c8 + 8, kh + row * D_ + c8 + 8);
            cp16(Bl + row * STRD + c8,     kl + row * D_ + c8);
            cp16(Bl + row * STRD + c8 + 8, kl + row * D_ + c8 + 8);
        }
    }
    CP_COMMIT();
    CP_WAIT0();
    __syncthreads();

    const int wid = tid >> 5, lane = tid & 31;
    const int g = lane >> 2, tg = lane & 3;
    const int wm = (wid >> 1) * 32;
    const int wn = (wid & 1) * 32;

    float c[2][4][4] = {};

#pragma unroll
    for (int k0 = 0; k0 < 64; k0 += 16) {
        u32 ah[2][4], al[2][4], bh[4][2], bl[4][2];
#pragma unroll
        for (int mi = 0; mi < 2; mi++) {
            const __half* ph = Ah + (wm + mi * 16 + g) * STRD + k0 + 2 * tg;
            ah[mi][0] = *(const u32*)(ph);
            ah[mi][1] = *(const u32*)(ph + 8 * STRD);
            ah[mi][2] = *(const u32*)(ph + 8);
            ah[mi][3] = *(const u32*)(ph + 8 * STRD + 8);
            const __half* pl = Al + (wm + mi * 16 + g) * STRD + k0 + 2 * tg;
            al[mi][0] = *(const u32*)(pl);
            al[mi][1] = *(const u32*)(pl + 8 * STRD);
            al[mi][2] = *(const u32*)(pl + 8);
            al[mi][3] = *(const u32*)(pl + 8 * STRD + 8);
        }
#pragma unroll
        for (int ni = 0; ni < 4; ni++) {
            const __half* ph = Bh + (wn + ni * 8 + g) * STRD + k0 + 2 * tg;
            bh[ni][0] = *(const u32*)(ph);
            bh[ni][1] = *(const u32*)(ph + 8);
            const __half* pl = Bl + (wn + ni * 8 + g) * STRD + k0 + 2 * tg;
            bl[ni][0] = *(const u32*)(pl);
            bl[ni][1] = *(const u32*)(pl + 8);
        }
#pragma unroll
        for (int mi = 0; mi < 2; mi++)
#pragma unroll
            for (int ni = 0; ni < 4; ni++) {
                mma_bf16(c[mi][ni], ah[mi][0], ah[mi][1], ah[mi][2], ah[mi][3],
                         bh[ni][0], bh[ni][1]);
                mma_bf16(c[mi][ni], al[mi][0], al[mi][1], al[mi][2], al[mi][3],
                         bh[ni][0], bh[ni][1]);
                mma_bf16(c[mi][ni], ah[mi][0], ah[mi][1], ah[mi][2], ah[mi][3],
                         bl[ni][0], bl[ni][1]);
            }
    }

    __syncthreads();
    __half* Es = Ah;   // [128][STRD]
#pragma unroll
    for (int mi = 0; mi < 2; mi++)
#pragma unroll
        for (int ni = 0; ni < 4; ni++) {
            int ml = wm + mi * 16 + g;
            int nl = wn + ni * 8 + 2 * tg;
            *(__half2*)&Es[ml * STRD + nl] =
                __floats2half2_rn(c[mi][ni][0], c[mi][ni][1]);
            *(__half2*)&Es[(ml + 8) * STRD + nl] =
                __floats2half2_rn(c[mi][ni][2], c[mi][ni][3]);
        }
    __syncthreads();
#pragma unroll
    for (int i = 0; i < 4; i++) {
        int idx = tid + i * 256;
        int row = idx >> 3;
        int c8  = (idx & 7) * 8;
        uint4 v = *(const uint4*)&Es[row * STRD + c8];
        *(uint4*)&Sb[(size_t)(qt + row) * TK_ + kt + c8] = v;
    }
}

// ---------------------------------------------------------------------------
// Kernel B: P(fp16) = exp(mask((S + Q·pos_k)/8)); emits partial rowsums.
// ---------------------------------------------------------------------------
__device__ __forceinline__ int bswz(int n, int c) {
    return n * 64 + ((((c >> 2) ^ (n & 7)) << 2) | (c & 3));
}
#define CSTR 132

extern "C" __global__ void __launch_bounds__(256)
posk_kernel(const float* __restrict__ PK, const int* __restrict__ VL)
{
    const int q  = blockIdx.y;
    const int kt = blockIdx.x * 128;

    __shared__ __nv_bfloat16 Ah[32][STRD], Al[32][STRD];
    __shared__ float Bs[128 * 64];        // pos_k fp32 swizzled; reused as Cs
    __shared__ float rsum2[32];
    __shared__ int vls[B_];

    const int tid = threadIdx.x;
    {
        int row = tid >> 3;
        int c8  = (tid & 7) * 8;
        cp16(&Ah[row][c8], g_Qh + ((size_t)row * TQ_ + q) * D_ + c8);
        cp16(&Al[row][c8], g_Ql + ((size_t)row * TQ_ + q) * D_ + c8);
    }
    {
        const float* PKq = PK + ((size_t)q * TK_ + kt) * D_;
#pragma unroll
        for (int i = 0; i < 8; i++) {
            int idx = tid + i * 256;
            int row = idx >> 4;
            int c4  = idx & 15;
            cp16(&Bs[row * 64 + ((c4 ^ (row & 7)) << 2)], PKq + row * 64 + c4 * 4);
        }
    }
    CP_COMMIT();
    if (tid < B_) vls[tid] = VL[tid];
    CP_WAIT0();
    __syncthreads();

    const int wid = tid >> 5, lane = tid & 31;
    const int g = lane >> 2, tg = lane & 3;
    const int wn = wid * 16;

    float c[2][2][4] = {};

#pragma unroll
    for (int k0 = 0; k0 < 64; k0 += 16) {
        u32 ah[2][4], al[2][4], bh[2][2], bl[2][2];
#pragma unroll
        for (int mi = 0; mi < 2; mi++) {
            const __nv_bfloat16* ph = &Ah[mi * 16 + g][k0 + 2 * tg];
            ah[mi][0] = *(const u32*)(ph);
            ah[mi][1] = *(const u32*)(ph + 8 * STRD);
            ah[mi][2] = *(const u32*)(ph + 8);
            ah[mi][3] = *(const u32*)(ph + 8 * STRD + 8);
            const __nv_bfloat16* pl = &Al[mi * 16 + g][k0 + 2 * tg];
            al[mi][0] = *(const u32*)(pl);
            al[mi][1] = *(const u32*)(pl + 8 * STRD);
            al[mi][2] = *(const u32*)(pl + 8);
            al[mi][3] = *(const u32*)(pl + 8 * STRD + 8);
        }
#pragma unroll
        for (int ni = 0; ni < 2; ni++) {
            const int n = wn + ni * 8 + g;
            float2 v0 = *(const float2*)&Bs[bswz(n, k0 + 2 * tg)];
            split2(v0.x, v0.y, bh[ni][0], bl[ni][0]);
            float2 v1 = *(const float2*)&Bs[bswz(n, k0 + 2 * tg + 8)];
            split2(v1.x, v1.y, bh[ni][1], bl[ni][1]);
        }
#pragma unroll
        for (int mi = 0; mi < 2; mi++)
#pragma unroll
            for (int ni = 0; ni < 2; ni++) {
                mma_bf16(c[mi][ni], ah[mi][0], ah[mi][1], ah[mi][2], ah[mi][3],
                         bh[ni][0], bh[ni][1]);
                mma_bf16(c[mi][ni], al[mi][0], al[mi][1], al[mi][2], al[mi][3],
                         bh[ni][0], bh[ni][1]);
                mma_bf16(c[mi][ni], ah[mi][0], ah[mi][1], ah[mi][2], ah[mi][3],
                         bl[ni][0], bl[ni][1]);
            }
    }

    __syncthreads();
    float* Cs = Bs;   // [32][CSTR]
#pragma unroll
    for (int mi = 0; mi < 2; mi++)
#pragma unroll
        for (int ni = 0; ni < 2; ni++) {
            const int b0  = mi * 16 + g;
            const int col = wn + ni * 8 + 2 * tg;
            *(float2*)&Cs[b0 * CSTR + col] =
                make_float2(c[mi][ni][0], c[mi][ni][1]);
            *(float2*)&Cs[(b0 + 8) * CSTR + col] =
                make_float2(c[mi][ni][2], c[mi][ni][3]);
        }
    __syncthreads();

#pragma unroll
    for (int i = 0; i < 2; i++) {
        int idx = tid + i * 256;
        int row = idx >> 4;
        int c8  = (idx & 15) * 8;
        uint4 sv = *(const uint4*)&g_S[((size_t)row * TQ_ + q) * TK_ + kt + c8];
        const int vl = vls[row];
        uint4 out;
        float sum8 = 0.f;
#pragma unroll
        for (int j = 0; j < 4; j++) {
            u32 sraw = ((const u32*)&sv)[j];
            float2 s = __half22float2(*(__half2*)&sraw);
            float cva = Cs[row * CSTR + c8 + 2 * j];
            float cvb = Cs[row * CSTR + c8 + 2 * j + 1];
            int col = kt + c8 + 2 * j;
            float e0 = (col     < vl) ? __expf((s.x + cva) * 0.125f) : 0.f;
            float e1 = (col + 1 < vl) ? __expf((s.y + cvb) * 0.125f) : 0.f;
            __half2 hp = __floats2half2_rn(e0, e1);
            ((u32*)&out)[j] = *(u32*)&hp;
            float2 er = __half22float2(hp);
            sum8 += er.x + er.y;
        }
        *(uint4*)&g_P[((size_t)row * TQ_ + q) * TK_ + kt + c8] = out;
        float v = sum8;
        v += __shfl_xor_sync(0xffffffffu, v, 1);
        v += __shfl_xor_sync(0xffffffffu, v, 2);
        v += __shfl_xor_sync(0xffffffffu, v, 4);
        v += __shfl_xor_sync(0xffffffffu, v, 8);
        if ((lane & 15) == 0) rsum2[row] = v;
    }
    __syncthreads();
    if (tid < 32)
        g_psum[((size_t)tid * TQ_ + q) * 8 + blockIdx.x] = rsum2[tid];
}

// ---------------------------------------------------------------------------
// Kernel C: MERGED pv + posv. grid 1536, interleaved 1:2 so both kinds are
// co-resident. pv part writes Out; posv part writes g_O2 (no race).
// Dynamic smem = 53.5 KB (pv layout is the larger).
// ---------------------------------------------------------------------------
#define PV_AH_BYTES (2 * 64 * STRD * 2)
#define PV_VS_BYTES (2 * 64 * VSTR * 4)
#define PV_SMEM     (PV_AH_BYTES + PV_VS_BYTES + 64 * 4)

extern "C" __global__ void __launch_bounds__(256)
pvposv_kernel(const float* __restrict__ V, const float* __restrict__ PV,
              float* __restrict__ Out)
{
    extern __shared__ char dynbuf[];
    const int bid = blockIdx.x;
    const int third = bid / 3;
    const int rem   = bid % 3;
    const int tid = threadIdx.x;
    const int wid = tid >> 5, lane = tid & 31;
    const int g = lane >> 2, tg = lane & 3;

    if (rem == 0) {
        // ---------------- pv path: third in [0,512) -> (bz, qt) ------------
        __half* AhB  = (__half*)dynbuf;                       // [2][64][STRD]
        float*  VsB  = (float*)(dynbuf + PV_AH_BYTES);        // [2][64][VSTR]
        float*  invs = (float*)(dynbuf + PV_AH_BYTES + PV_VS_BYTES);

        const int bz = third >> 4;
        const int qt = (third & 15) * 64;
        const float* Vb = V + (size_t)bz * TK_ * D_;
        const __half* Pb = g_P + (size_t)bz * TQ_ * TK_;

        if (tid < 64) {
            const float* ps = &g_psum[((size_t)bz * TQ_ + qt + tid) * 8];
            float4 a = *(const float4*)ps;
            float4 b = *(const float4*)(ps + 4);
            invs[tid] = 1.0f / (((a.x + a.y) + (a.z + a.w)) + ((b.x + b.y) + (b.z + b.w)));
        }

        auto load_stage = [&](int s, int kt) {
            __half* A = AhB + s * 64 * STRD;
            float*  Vt = VsB + s * 64 * VSTR;
#pragma unroll
            for (int i = 0; i < 2; i++) {
                int idx = tid + i * 256;
                int r  = idx >> 3;
                int kc = (idx & 7) * 8;
                cp16(A + r * STRD + kc, Pb + (size_t)(qt + r) * TK_ + kt + kc);
            }
#pragma unroll
            for (int i = 0; i < 4; i++) {
                int idx = tid + i * 256;
                int k  = idx >> 4;
                int dc = (idx & 15) * 4;
                cp16(Vt + k * VSTR + dc, Vb + (size_t)(kt + k) * D_ + dc);
            }
            CP_COMMIT();
        };

        const int wm = (wid >> 2) * 32;
        const int wn = (wid & 3) * 16;

        float c[2][2][4] = {};

        load_stage(0, 0);
        for (int ci = 0; ci < 16; ci++) {
            const int s = ci & 1;
            if (ci < 15) { load_stage(s ^ 1, (ci + 1) * 64); CP_WAIT1(); }
            else         { CP_WAIT0(); }
            __syncthreads();

            const __half* A = AhB + s * 64 * STRD;
            const float*  Vt = VsB + s * 64 * VSTR;
#pragma unroll
            for (int k0 = 0; k0 < 64; k0 += 16) {
                u32 a[2][4], bh[2][2], bl[2][2];
#pragma unroll
                for (int mi = 0; mi < 2; mi++) {
                    const __half* ph = A + (wm + mi * 16 + g) * STRD + k0 + 2 * tg;
                    a[mi][0] = *(const u32*)(ph);
                    a[mi][1] = *(const u32*)(ph + 8 * STRD);
                    a[mi][2] = *(const u32*)(ph + 8);
                    a[mi][3] = *(const u32*)(ph + 8 * STRD + 8);
                }
#pragma unroll
                for (int ni = 0; ni < 2; ni++) {
                    const int n = wn + ni * 8 + g;
                    const int kb = k0 + 2 * tg;
                    split2h(Vt[kb * VSTR + n],       Vt[(kb + 1) * VSTR + n], bh[ni][0], bl[ni][0]);
                    split2h(Vt[(kb + 8) * VSTR + n], Vt[(kb + 9) * VSTR + n], bh[ni][1], bl[ni][1]);
                }
#pragma unroll
                for (int mi = 0; mi < 2; mi++)
#pragma unroll
                    for (int ni = 0; ni < 2; ni++) {
                        mma_f16(c[mi][ni], a[mi][0], a[mi][1], a[mi][2], a[mi][3],
                                bh[ni][0], bh[ni][1]);
                        mma_f16(c[mi][ni], a[mi][0], a[mi][1], a[mi][2], a[mi][3],
                                bl[ni][0], bl[ni][1]);
                    }
            }
            __syncthreads();
        }

#pragma unroll
        for (int mi = 0; mi < 2; mi++)
#pragma unroll
            for (int ni = 0; ni < 2; ni++) {
                int m = wm + mi * 16 + g;
                int n = wn + ni * 8 + 2 * tg;
                float inv0 = invs[m], inv1 = invs[m + 8];
                float* d0 = Out + ((size_t)bz * TQ_ + qt + m) * D_ + n;
                *(float2*)d0 = make_float2(c[mi][ni][0] * inv0, c[mi][ni][1] * inv0);
                float* d1 = Out + ((size_t)bz * TQ_ + qt + m + 8) * D_ + n;
                *(float2*)d1 = make_float2(c[mi][ni][2] * inv1, c[mi][ni][3] * inv1);
            }
    } else {
        // ---------------- posv path: q in [0,1024) -------------------------
        const int q = third * 2 + (rem - 1);

        __half* Ahs  = (__half*)dynbuf;                       // [2][32][STRD]
        float*  PVs  = (float*)(dynbuf + 2 * 32 * STRD * 2);  // [2][64][VSTR]
        float*  invs = (float*)(dynbuf + 2 * 32 * STRD * 2 + 2 * 64 * VSTR * 4);

        if (tid < B_) {
            const float* ps = &g_psum[((size_t)tid * TQ_ + q) * 8];
            float4 a = *(const float4*)ps;
            float4 b = *(const float4*)(ps + 4);
            invs[tid] = 1.0f / (((a.x + a.y) + (a.z + a.w)) + ((b.x + b.y) + (b.z + b.w)));
        }

        auto load_stage = [&](int s, int kt) {
            {
                int bb = tid >> 3;
                int kc = (tid & 7) * 8;
                cp16(Ahs + (s * 32 + bb) * STRD + kc,
                     g_P + ((size_t)bb * TQ_ + q) * TK_ + kt + kc);
            }
            const float* PVq = PV + ((size_t)q * TK_ + kt) * D_;
#pragma unroll
            for (int i = 0; i < 4; i++) {
                int idx = tid + i * 256;
                int k  = idx >> 4;
                int dc = (idx & 15) * 4;
                cp16(PVs + (s * 64 + k) * VSTR + dc, PVq + (size_t)k * D_ + dc);
            }
            CP_COMMIT();
        };

        const int wn = wid * 8;

        float c[2][4] = {};

        load_stage(0, 0);
        for (int ci = 0; ci < 16; ci++) {
            const int s = ci & 1;
            if (ci < 15) { load_stage(s ^ 1, (ci + 1) * 64); CP_WAIT1(); }
            else         { CP_WAIT0(); }
            __syncthreads();

#pragma unroll
            for (int k0 = 0; k0 < 64; k0 += 16) {
                u32 a[2][4], bh[2], bl[2];
#pragma unroll
                for (int mi = 0; mi < 2; mi++) {
                    const __half* ph = Ahs + (s * 32 + mi * 16 + g) * STRD + k0 + 2 * tg;
                    a[mi][0] = *(const u32*)(ph);
                    a[mi][1] = *(const u32*)(ph + 8 * STRD);
                    a[mi][2] = *(const u32*)(ph + 8);
                    a[mi][3] = *(const u32*)(ph + 8 * STRD + 8);
                }
                {
                    const int n = wn + g;
                    const int kb = k0 + 2 * tg;
                    split2h(PVs[(s * 64 + kb) * VSTR + n],
                            PVs[(s * 64 + kb + 1) * VSTR + n], bh[0], bl[0]);
                    split2h(PVs[(s * 64 + kb + 8) * VSTR + n],
                            PVs[(s * 64 + kb + 9) * VSTR + n], bh[1], bl[1]);
                }
#pragma unroll
                for (int mi = 0; mi < 2; mi++) {
                    mma_f16(c[mi], a[mi][0], a[mi][1], a[mi][2], a[mi][3], bh[0], bh[1]);
                    mma_f16(c[mi], a[mi][0], a[mi][1], a[mi][2], a[mi][3], bl[0], bl[1]);
                }
            }
            __syncthreads();
        }

#pragma unroll
        for (int mi = 0; mi < 2; mi++) {
            const int b0 = mi * 16 + g;
            const int b1 = b0 + 8;
            const int n  = wn + 2 * tg;
            float* d0 = g_O2 + ((size_t)b0 * TQ_ + q) * D_ + n;
            *(float2*)d0 = make_float2(c[mi][0] * invs[b0], c[mi][1] * invs[b0]);
            float* d1 = g_O2 + ((size_t)b1 * TQ_ + q) * D_ + n;
            *(float2*)d1 = make_float2(c[mi][2] * invs[b1], c[mi][3] * invs[b1]);
        }
    }
}

// ---------------------------------------------------------------------------
// Kernel E: Out += g_O2 (content + pos contributions). 2M floats.
// ---------------------------------------------------------------------------
extern "C" __global__ void __launch_bounds__(256)
add_kernel(float* __restrict__ Out)
{
    size_t idx = (size_t)blockIdx.x * 256 + threadIdx.x;
    float4 o = ((const float4*)Out)[idx];
    float4 a = ((const float4*)g_O2)[idx];
    o.x += a.x; o.y += a.y; o.z += a.z; o.w += a.w;
    ((float4*)Out)[idx] = o;
}

// ---------------------------------------------------------------------------
extern "C" void kernel_launch(void* const* d_in, const int* in_sizes, int n_in,
                              void* d_out, int out_size)
{
    const float* Q  = (const float*)d_in[0];
    const float* K  = (const float*)d_in[1];
    const float* V  = (const float*)d_in[2];
    const float* PK = (const float*)d_in[3];
    const float* PV = (const float*)d_in[4];
    const int*   VL = (const int*)d_in[5];
    float* Out = (float*)d_out;

    cudaFuncSetAttribute(qk_kernel, cudaFuncAttributeMaxDynamicSharedMemorySize,
                         QK_SMEM);
    cudaFuncSetAttribute(pvposv_kernel, cudaFuncAttributeMaxDynamicSharedMemorySize,
                         PV_SMEM);

    prep_qk_kernel<<<2048, 256>>>(Q, K);
    qk_kernel<<<dim3(TK_ / 64, TQ_ / 128, B_), 256, QK_SMEM>>>();
    posk_kernel<<<dim3(TK_ / 128, TQ_), 256>>>(PK, VL);
    pvposv_kernel<<<1536, 256, PV_SMEM>>>(V, PV, Out);
    add_kernel<<<2048, 256>>>(Out);
}